// round 13
// baseline (speedup 1.0000x reference)
#include <cuda_runtime.h>
#include <cuda_bf16.h>
#include <math.h>

// ---------------- problem constants ----------------
#define BATCH 4
#define NROI 1632
#define DIN 1632
#define DMODEL 256
#define NHEAD 4
#define DHEAD 64
#define DFF 1024
#define SEQ 3375          // 15^3
#define ROWS_X (BATCH*SEQ)   // 13500
#define ROWS_Q (BATCH*NROI)  // 6528
#define LN_EPS 1e-5f

// ---------------- scratch (device globals; no allocation allowed) ----------------
__device__ float g_Q[ROWS_Q * DMODEL];
__device__ float g_x[ROWS_X * DMODEL];
__device__ float g_x2[ROWS_X * DMODEL];
__device__ float g_q[BATCH * NHEAD * SEQ * DHEAD];
__device__ float g_k[BATCH * NHEAD * SEQ * DHEAD];
__device__ float g_v[BATCH * NHEAD * SEQ * DHEAD];
__device__ float g_o[ROWS_X * DMODEL];
__device__ float g_t[ROWS_X * DMODEL];
__device__ float g_h[ROWS_X * DFF];
__device__ float g_y[ROWS_X * DMODEL];
__device__ float g_part[BATCH * 8 * DMODEL];

// ---------------- helpers ----------------
__device__ __forceinline__ float gelu_exact(float x) {
    return 0.5f * x * (1.0f + erff(x * 0.70710678118654752f));
}
__device__ __forceinline__ float to_tf32(float x) {
    float r;
    asm("cvt.rna.tf32.f32 %0, %1;" : "=f"(r) : "f"(x));
    return r;
}
__device__ __forceinline__ void mma_tf32(float* d, const unsigned* a,
                                         unsigned b0, unsigned b1) {
    asm volatile(
        "mma.sync.aligned.m16n8k8.row.col.f32.tf32.tf32.f32 "
        "{%0,%1,%2,%3}, {%4,%5,%6,%7}, {%8,%9}, {%0,%1,%2,%3};\n"
        : "+f"(d[0]), "+f"(d[1]), "+f"(d[2]), "+f"(d[3])
        : "r"(a[0]), "r"(a[1]), "r"(a[2]), "r"(a[3]), "r"(b0), "r"(b1));
}
// ldmatrix x4: loads four 8x8 b16-matrices (here: 8 rows x 4 f32 each).
__device__ __forceinline__ void ldsm4(unsigned& r0, unsigned& r1, unsigned& r2,
                                      unsigned& r3, unsigned addr) {
    asm volatile("ldmatrix.sync.aligned.m8n8.x4.shared.b16 {%0,%1,%2,%3}, [%4];"
                 : "=r"(r0), "=r"(r1), "=r"(r2), "=r"(r3) : "r"(addr));
}
// hi/lo split of a float4 into interleaved {h,l} pairs (A operand: exact split).
__device__ __forceinline__ void hl4(float4 v, float4& o0, float4& o1) {
    float hx = to_tf32(v.x), hy = to_tf32(v.y), hz = to_tf32(v.z), hw = to_tf32(v.w);
    o0 = make_float4(hx, v.x - hx, hy, v.y - hy);
    o1 = make_float4(hz, v.z - hz, hw, v.w - hw);
}
__device__ __forceinline__ float4 tf4(float4 v) {
    return make_float4(to_tf32(v.x), to_tf32(v.y), to_tf32(v.z), to_tf32(v.w));
}

// ---------------- tensor-core 2xTF32 GEMM, double-buffered, 128x64 tile ----------------
#define GBM 128
#define GBN 64
#define GBK 16
#define GSTRA 40
#define GSTRB 20
#define G_A (GBM * GSTRA)
#define G_Bf (GBN * GSTRB)
#define G_BUF (G_A + G_Bf)
#define G_SMEM (2 * G_BUF * 4)

__global__ void __launch_bounds__(256, 2)
gemm2t(const float* __restrict__ A, const float* __restrict__ B,
       const float* __restrict__ bias, float* __restrict__ C,
       int M, int N, int K, int act,
       float* __restrict__ qp, float* __restrict__ kp, float* __restrict__ vp) {
    extern __shared__ float smg[];

    const int bm = blockIdx.y * GBM;
    const int bn = blockIdx.x * GBN;
    const int tid = threadIdx.x;
    const int warp = tid >> 5, lane = tid & 31;
    const int g = lane >> 2, t = lane & 3;
    const int wm = warp >> 1, wn = warp & 1;

    const int am = tid >> 1, ac = tid & 1;
    const int bnr = tid >> 2, bq = tid & 3;
    const int arow = bm + am;
    const int brow = bn + bnr;

    float acc[2][4][4];
#pragma unroll
    for (int mi = 0; mi < 2; mi++)
#pragma unroll
        for (int ni = 0; ni < 4; ni++)
#pragma unroll
            for (int v = 0; v < 4; v++) acc[mi][ni][v] = 0.f;

    const int niter = K / GBK;

    float4 ra0, ra1, rb;
    {
        ra0 = make_float4(0.f, 0.f, 0.f, 0.f);
        ra1 = ra0;
        if (arow < M) {
            ra0 = *reinterpret_cast<const float4*>(&A[(size_t)arow * K + 8 * ac]);
            ra1 = *reinterpret_cast<const float4*>(&A[(size_t)arow * K + 8 * ac + 4]);
        }
        rb = *reinterpret_cast<const float4*>(&B[(size_t)brow * K + 4 * bq]);
        float* Abuf = smg;
        float* Bbuf = smg + G_A;
        float4 o0, o1;
        hl4(ra0, o0, o1);
        *reinterpret_cast<float4*>(&Abuf[am * GSTRA + 16 * ac]) = o0;
        *reinterpret_cast<float4*>(&Abuf[am * GSTRA + 16 * ac + 4]) = o1;
        hl4(ra1, o0, o1);
        *reinterpret_cast<float4*>(&Abuf[am * GSTRA + 16 * ac + 8]) = o0;
        *reinterpret_cast<float4*>(&Abuf[am * GSTRA + 16 * ac + 12]) = o1;
        *reinterpret_cast<float4*>(&Bbuf[bnr * GSTRB + 4 * bq]) = tf4(rb);
    }
    __syncthreads();

    for (int it = 0; it < niter; it++) {
        const int buf = it & 1;
        const bool have_next = (it + 1 < niter);
        if (have_next) {
            int k0 = (it + 1) * GBK;
            ra0 = make_float4(0.f, 0.f, 0.f, 0.f);
            ra1 = ra0;
            if (arow < M) {
                ra0 = *reinterpret_cast<const float4*>(&A[(size_t)arow * K + k0 + 8 * ac]);
                ra1 = *reinterpret_cast<const float4*>(&A[(size_t)arow * K + k0 + 8 * ac + 4]);
            }
            rb = *reinterpret_cast<const float4*>(&B[(size_t)brow * K + k0 + 4 * bq]);
        }

        {
            const float2* A2 = reinterpret_cast<const float2*>(smg + buf * G_BUF);
            const float* Bs = smg + buf * G_BUF + G_A;
#pragma unroll
            for (int kc = 0; kc < 2; kc++) {
                unsigned ah[2][4], al[2][4];
#pragma unroll
                for (int mi = 0; mi < 2; mi++) {
                    int m0 = wm * 32 + mi * 16;
                    int kk = kc * 8 + t;
                    float2 p;
                    p = A2[(m0 + g) * 20 + kk];
                    ah[mi][0] = __float_as_uint(p.x); al[mi][0] = __float_as_uint(p.y);
                    p = A2[(m0 + g + 8) * 20 + kk];
                    ah[mi][1] = __float_as_uint(p.x); al[mi][1] = __float_as_uint(p.y);
                    p = A2[(m0 + g) * 20 + kk + 4];
                    ah[mi][2] = __float_as_uint(p.x); al[mi][2] = __float_as_uint(p.y);
                    p = A2[(m0 + g + 8) * 20 + kk + 4];
                    ah[mi][3] = __float_as_uint(p.x); al[mi][3] = __float_as_uint(p.y);
                }
                unsigned bh[4][2];
#pragma unroll
                for (int ni = 0; ni < 4; ni++) {
                    int n0 = wn * 32 + ni * 8;
                    int kk = kc * 8 + t;
                    bh[ni][0] = __float_as_uint(Bs[(n0 + g) * GSTRB + kk]);
                    bh[ni][1] = __float_as_uint(Bs[(n0 + g) * GSTRB + kk + 4]);
                }
#pragma unroll
                for (int mi = 0; mi < 2; mi++)
#pragma unroll
                    for (int ni = 0; ni < 4; ni++) {
                        mma_tf32(acc[mi][ni], ah[mi], bh[ni][0], bh[ni][1]);
                        mma_tf32(acc[mi][ni], al[mi], bh[ni][0], bh[ni][1]);
                    }
            }
        }

        if (have_next) {
            float* Abuf = smg + (buf ^ 1) * G_BUF;
            float* Bbuf = Abuf + G_A;
            float4 o0, o1;
            hl4(ra0, o0, o1);
            *reinterpret_cast<float4*>(&Abuf[am * GSTRA + 16 * ac]) = o0;
            *reinterpret_cast<float4*>(&Abuf[am * GSTRA + 16 * ac + 4]) = o1;
            hl4(ra1, o0, o1);
            *reinterpret_cast<float4*>(&Abuf[am * GSTRA + 16 * ac + 8]) = o0;
            *reinterpret_cast<float4*>(&Abuf[am * GSTRA + 16 * ac + 12]) = o1;
            *reinterpret_cast<float4*>(&Bbuf[bnr * GSTRB + 4 * bq]) = tf4(rb);
        }
        __syncthreads();
    }

    if (act != 2) {
#pragma unroll
        for (int mi = 0; mi < 2; mi++) {
            int m0 = bm + wm * 32 + mi * 16;
            int row0 = m0 + g;
            int row1 = m0 + g + 8;
#pragma unroll
            for (int ni = 0; ni < 4; ni++) {
                int col = bn + wn * 32 + ni * 8 + 2 * t;
                float b0 = bias[col], b1 = bias[col + 1];
                if (row0 < M) {
                    float v0 = acc[mi][ni][0] + b0;
                    float v1 = acc[mi][ni][1] + b1;
                    if (act == 1) { v0 = gelu_exact(v0); v1 = gelu_exact(v1); }
                    *reinterpret_cast<float2*>(&C[(size_t)row0 * N + col]) = make_float2(v0, v1);
                }
                if (row1 < M) {
                    float v2 = acc[mi][ni][2] + b0;
                    float v3 = acc[mi][ni][3] + b1;
                    if (act == 1) { v2 = gelu_exact(v2); v3 = gelu_exact(v3); }
                    *reinterpret_cast<float2*>(&C[(size_t)row1 * N + col]) = make_float2(v2, v3);
                }
            }
        }
    } else {
        // qkv-split epilogue
#pragma unroll
        for (int mi = 0; mi < 2; mi++) {
            int m0 = bm + wm * 32 + mi * 16;
#pragma unroll
            for (int ni = 0; ni < 4; ni++) {
                int col = bn + wn * 32 + ni * 8 + 2 * t;
                int sec = col >> 8;
                int d = col & 255;
                int h = d >> 6;
                int dh = d & 63;
                float* dst = (sec == 0) ? qp : (sec == 1) ? kp : vp;
                float scale = (sec == 0) ? 0.125f : 1.f;
                float b0 = bias[col], b1 = bias[col + 1];
                int row0 = m0 + g;
                int row1 = m0 + g + 8;
                if (row0 < M) {
                    int b = row0 / SEQ, s = row0 - b * SEQ;
                    size_t base = ((size_t)(b * NHEAD + h) * SEQ + s) * DHEAD + dh;
                    *reinterpret_cast<float2*>(&dst[base]) =
                        make_float2((acc[mi][ni][0] + b0) * scale, (acc[mi][ni][1] + b1) * scale);
                }
                if (row1 < M) {
                    int b = row1 / SEQ, s = row1 - b * SEQ;
                    size_t base = ((size_t)(b * NHEAD + h) * SEQ + s) * DHEAD + dh;
                    *reinterpret_cast<float2*>(&dst[base]) =
                        make_float2((acc[mi][ni][2] + b0) * scale, (acc[mi][ni][3] + b1) * scale);
                }
            }
        }
    }
}

// ---------------- 64x64-tile variant (128 threads) for small-grid GEMMs ----------------
#define HBM64 64
#define H_A (HBM64 * GSTRA)
#define H_B (HBM64 * GSTRB)
#define H_BUF (H_A + H_B)
#define H_SMEM (2 * H_BUF * 4)

__global__ void __launch_bounds__(128, 4)
gemm64(const float* __restrict__ A, const float* __restrict__ B,
       const float* __restrict__ bias, float* __restrict__ C,
       int M, int N, int K, int act, const float* __restrict__ R) {
    extern __shared__ float smg[];

    const int bm = blockIdx.y * HBM64;
    const int bn = blockIdx.x * HBM64;
    const int tid = threadIdx.x;
    const int warp = tid >> 5, lane = tid & 31;
    const int g = lane >> 2, t = lane & 3;
    const int wm = warp >> 1, wn = warp & 1;

    const int am = tid >> 1, ac = tid & 1;
    const int bnr = tid >> 1;
    const int bq0 = (tid & 1) * 2;
    const int arow = bm + am;
    const int brow = bn + bnr;

    float acc[2][4][4];
#pragma unroll
    for (int mi = 0; mi < 2; mi++)
#pragma unroll
        for (int ni = 0; ni < 4; ni++)
#pragma unroll
            for (int v = 0; v < 4; v++) acc[mi][ni][v] = 0.f;

    const int niter = K / GBK;

    float4 ra0, ra1, rb0, rb1;
    {
        ra0 = make_float4(0.f, 0.f, 0.f, 0.f);
        ra1 = ra0;
        if (arow < M) {
            ra0 = *reinterpret_cast<const float4*>(&A[(size_t)arow * K + 8 * ac]);
            ra1 = *reinterpret_cast<const float4*>(&A[(size_t)arow * K + 8 * ac + 4]);
        }
        rb0 = *reinterpret_cast<const float4*>(&B[(size_t)brow * K + 4 * bq0]);
        rb1 = *reinterpret_cast<const float4*>(&B[(size_t)brow * K + 4 * bq0 + 4]);
        float* Abuf = smg;
        float* Bbuf = smg + H_A;
        float4 o0, o1;
        hl4(ra0, o0, o1);
        *reinterpret_cast<float4*>(&Abuf[am * GSTRA + 16 * ac]) = o0;
        *reinterpret_cast<float4*>(&Abuf[am * GSTRA + 16 * ac + 4]) = o1;
        hl4(ra1, o0, o1);
        *reinterpret_cast<float4*>(&Abuf[am * GSTRA + 16 * ac + 8]) = o0;
        *reinterpret_cast<float4*>(&Abuf[am * GSTRA + 16 * ac + 12]) = o1;
        *reinterpret_cast<float4*>(&Bbuf[bnr * GSTRB + 4 * bq0]) = tf4(rb0);
        *reinterpret_cast<float4*>(&Bbuf[bnr * GSTRB + 4 * bq0 + 4]) = tf4(rb1);
    }
    __syncthreads();

    for (int it = 0; it < niter; it++) {
        const int buf = it & 1;
        const bool have_next = (it + 1 < niter);
        if (have_next) {
            int k0 = (it + 1) * GBK;
            ra0 = make_float4(0.f, 0.f, 0.f, 0.f);
            ra1 = ra0;
            if (arow < M) {
                ra0 = *reinterpret_cast<const float4*>(&A[(size_t)arow * K + k0 + 8 * ac]);
                ra1 = *reinterpret_cast<const float4*>(&A[(size_t)arow * K + k0 + 8 * ac + 4]);
            }
            rb0 = *reinterpret_cast<const float4*>(&B[(size_t)brow * K + k0 + 4 * bq0]);
            rb1 = *reinterpret_cast<const float4*>(&B[(size_t)brow * K + k0 + 4 * bq0 + 4]);
        }

        {
            const float2* A2 = reinterpret_cast<const float2*>(smg + buf * H_BUF);
            const float* Bs = smg + buf * H_BUF + H_A;
#pragma unroll
            for (int kc = 0; kc < 2; kc++) {
                unsigned ah[2][4], al[2][4];
#pragma unroll
                for (int mi = 0; mi < 2; mi++) {
                    int m0 = wm * 32 + mi * 16;
                    int kk = kc * 8 + t;
                    float2 p;
                    p = A2[(m0 + g) * 20 + kk];
                    ah[mi][0] = __float_as_uint(p.x); al[mi][0] = __float_as_uint(p.y);
                    p = A2[(m0 + g + 8) * 20 + kk];
                    ah[mi][1] = __float_as_uint(p.x); al[mi][1] = __float_as_uint(p.y);
                    p = A2[(m0 + g) * 20 + kk + 4];
                    ah[mi][2] = __float_as_uint(p.x); al[mi][2] = __float_as_uint(p.y);
                    p = A2[(m0 + g + 8) * 20 + kk + 4];
                    ah[mi][3] = __float_as_uint(p.x); al[mi][3] = __float_as_uint(p.y);
                }
                unsigned bh[4][2];
#pragma unroll
                for (int ni = 0; ni < 4; ni++) {
                    int n0 = wn * 32 + ni * 8;
                    int kk = kc * 8 + t;
                    bh[ni][0] = __float_as_uint(Bs[(n0 + g) * GSTRB + kk]);
                    bh[ni][1] = __float_as_uint(Bs[(n0 + g) * GSTRB + kk + 4]);
                }
#pragma unroll
                for (int mi = 0; mi < 2; mi++)
#pragma unroll
                    for (int ni = 0; ni < 4; ni++) {
                        mma_tf32(acc[mi][ni], ah[mi], bh[ni][0], bh[ni][1]);
                        mma_tf32(acc[mi][ni], al[mi], bh[ni][0], bh[ni][1]);
                    }
            }
        }

        if (have_next) {
            float* Abuf = smg + (buf ^ 1) * H_BUF;
            float* Bbuf = Abuf + H_A;
            float4 o0, o1;
            hl4(ra0, o0, o1);
            *reinterpret_cast<float4*>(&Abuf[am * GSTRA + 16 * ac]) = o0;
            *reinterpret_cast<float4*>(&Abuf[am * GSTRA + 16 * ac + 4]) = o1;
            hl4(ra1, o0, o1);
            *reinterpret_cast<float4*>(&Abuf[am * GSTRA + 16 * ac + 8]) = o0;
            *reinterpret_cast<float4*>(&Abuf[am * GSTRA + 16 * ac + 12]) = o1;
            *reinterpret_cast<float4*>(&Bbuf[bnr * GSTRB + 4 * bq0]) = tf4(rb0);
            *reinterpret_cast<float4*>(&Bbuf[bnr * GSTRB + 4 * bq0 + 4]) = tf4(rb1);
        }
        __syncthreads();
    }

#pragma unroll
    for (int mi = 0; mi < 2; mi++) {
        int m0 = bm + wm * 32 + mi * 16;
        int row0 = m0 + g;
        int row1 = m0 + g + 8;
#pragma unroll
        for (int ni = 0; ni < 4; ni++) {
            int col = bn + wn * 32 + ni * 8 + 2 * t;
            float b0 = bias[col], b1 = bias[col + 1];
            if (row0 < M) {
                float v0 = acc[mi][ni][0] + b0;
                float v1 = acc[mi][ni][1] + b1;
                if (act == 1) { v0 = gelu_exact(v0); v1 = gelu_exact(v1); }
                if (act == 3) {
                    float2 r2 = *reinterpret_cast<const float2*>(&R[(size_t)row0 * N + col]);
                    v0 += r2.x; v1 += r2.y;
                }
                *reinterpret_cast<float2*>(&C[(size_t)row0 * N + col]) = make_float2(v0, v1);
            }
            if (row1 < M) {
                float v2 = acc[mi][ni][2] + b0;
                float v3 = acc[mi][ni][3] + b1;
                if (act == 1) { v2 = gelu_exact(v2); v3 = gelu_exact(v3); }
                if (act == 3) {
                    float2 r2 = *reinterpret_cast<const float2*>(&R[(size_t)row1 * N + col]);
                    v2 += r2.x; v3 += r2.y;
                }
                *reinterpret_cast<float2*>(&C[(size_t)row1 * N + col]) = make_float2(v2, v3);
            }
        }
    }
}

// ---------------- gather + sum-pool ----------------
__global__ void gather_pool(const float* __restrict__ Q, const int* __restrict__ C,
                            float* __restrict__ out) {
    int o = blockIdx.x;
    int b = blockIdx.y;
    int d = threadIdx.x;
    int oz = o % 15;
    int oy = (o / 15) % 15;
    int ox = o / 225;
    const float* Qb = Q + (size_t)b * NROI * DMODEL;
    const int* Cb = C + (size_t)b * 32 * 32 * 32;
    float acc = 0.f;
#pragma unroll
    for (int dx = 0; dx < 3; dx++) {
        int x = 2 * ox + dx;
#pragma unroll
        for (int dy = 0; dy < 3; dy++) {
            int y = 2 * oy + dy;
#pragma unroll
            for (int dz = 0; dz < 3; dz++) {
                int z = 2 * oz + dz;
                int idx = Cb[(x * 32 + y) * 32 + z];
                acc += Qb[(size_t)idx * DMODEL + d];
            }
        }
    }
    out[((size_t)b * SEQ + o) * DMODEL + d] = acc;
}

// ---------------- flash attention: ldmatrix fragment loads ----------------
// Ks [64][68] (key-major), Vt [64][68] (TRANSPOSED: d-major), Ps [64][68].
// Pad 68 => ldmatrix row stride = 4 banks mod 32: conflict-free 8x16B fetch.
#define KPAD 68
#define VTPAD 68
#define FA_SMEM ((64*KPAD + 64*VTPAD + 64*KPAD) * 4)

__global__ void __launch_bounds__(128, 3)
flash_tf32(const float* __restrict__ Qm, const float* __restrict__ Km,
           const float* __restrict__ Vm, float* __restrict__ O) {
    extern __shared__ float sm[];
    float* Ks = sm;                         // [64][KPAD]
    float* Vt = sm + 64 * KPAD;             // [64 d][VTPAD]
    float* Ps = sm + 64 * KPAD + 64 * VTPAD; // [64][KPAD]

    const int bh = blockIdx.y;
    const int q0 = blockIdx.x * 64;
    const int tid = threadIdx.x;
    const int warp = tid >> 5;
    const int lane = tid & 31;
    const int g = lane >> 2;
    const int t = lane & 3;
    const int lm = lane >> 3;   // ldmatrix matrix index 0..3
    const int lr = lane & 7;    // ldmatrix row index 0..7

    const unsigned ks_u = (unsigned)__cvta_generic_to_shared(Ks);
    const unsigned vt_u = (unsigned)__cvta_generic_to_shared(Vt);
    const unsigned ps_u = (unsigned)__cvta_generic_to_shared(Ps);

    const float* qb = Qm + (size_t)bh * SEQ * DHEAD;
    const float* kb = Km + (size_t)bh * SEQ * DHEAD;
    const float* vb = Vm + (size_t)bh * SEQ * DHEAD;

    // stage Q tile (tf32) into Ps
#pragma unroll
    for (int it = 0; it < 8; it++) {
        int idx = tid + it * 128;
        int row = idx >> 4;
        int c4 = (idx & 15) << 2;
        float4 v = make_float4(0.f, 0.f, 0.f, 0.f);
        if (q0 + row < SEQ) v = *reinterpret_cast<const float4*>(&qb[(size_t)(q0 + row) * 64 + c4]);
        *reinterpret_cast<float4*>(&Ps[row * KPAD + c4]) = tf4(v);
    }
    __syncthreads();

    const int pr = 16 * warp;
    unsigned qa[8][4];
#pragma unroll
    for (int kc = 0; kc < 8; kc++) {
        qa[kc][0] = __float_as_uint(Ps[(pr + g) * KPAD + kc * 8 + t]);
        qa[kc][1] = __float_as_uint(Ps[(pr + g + 8) * KPAD + kc * 8 + t]);
        qa[kc][2] = __float_as_uint(Ps[(pr + g) * KPAD + kc * 8 + t + 4]);
        qa[kc][3] = __float_as_uint(Ps[(pr + g + 8) * KPAD + kc * 8 + t + 4]);
    }

    float oc[8][4];
    float mi[2] = {-1e30f, -1e30f};
    float li[2] = {0.f, 0.f};
#pragma unroll
    for (int n = 0; n < 8; n++)
#pragma unroll
        for (int v = 0; v < 4; v++) oc[n][v] = 0.f;

    // per-thread ldmatrix address bases (element offsets within arrays)
    // K / Vt B-fragments: row = (n0 + (lm>>1))*8 + lr ; col = kc*8 + (lm&1)*4
    const int bf_row = (lm >> 1) * 8 + lr;     // add n0*8
    const int bf_col = (lm & 1) * 4;           // add kc*8
    // P A-fragment: row = pr + (lm&1)*8 + lr ; col = kc*8 + (lm>>1)*4
    const int pa_row = pr + (lm & 1) * 8 + lr;
    const int pa_col = (lm >> 1) * 4;

    const int nkt = (SEQ + 63) / 64;
    for (int kt = 0; kt < nkt; kt++) {
        int k0 = kt * 64;
        // stage K (row-major) — 8 iters
#pragma unroll
        for (int it = 0; it < 8; it++) {
            int idx = tid + it * 128;
            int row = idx >> 4;
            int c4 = (idx & 15) << 2;
            float4 kv = make_float4(0.f, 0.f, 0.f, 0.f);
            if (k0 + row < SEQ)
                kv = *reinterpret_cast<const float4*>(&kb[(size_t)(k0 + row) * 64 + c4]);
            *reinterpret_cast<float4*>(&Ks[row * KPAD + c4]) = tf4(kv);
        }
        // stage V TRANSPOSED: thread handles (key = idx&63, c4 = (idx>>6)*4)
#pragma unroll
        for (int it = 0; it < 8; it++) {
            int idx = tid + it * 128;
            int key = idx & 63;
            int c4 = (idx >> 6) << 2;
            float4 vv = make_float4(0.f, 0.f, 0.f, 0.f);
            if (k0 + key < SEQ)
                vv = *reinterpret_cast<const float4*>(&vb[(size_t)(k0 + key) * 64 + c4]);
            vv = tf4(vv);
            Vt[(c4 + 0) * VTPAD + key] = vv.x;
            Vt[(c4 + 1) * VTPAD + key] = vv.y;
            Vt[(c4 + 2) * VTPAD + key] = vv.z;
            Vt[(c4 + 3) * VTPAD + key] = vv.w;
        }
        __syncthreads();

        // ---- S = Q K^T via ldmatrix B fragments ----
        float sf[8][4];
#pragma unroll
        for (int n = 0; n < 8; n++) { sf[n][0] = sf[n][1] = sf[n][2] = sf[n][3] = 0.f; }
#pragma unroll
        for (int kc = 0; kc < 8; kc++) {
#pragma unroll
            for (int n0 = 0; n0 < 8; n0 += 2) {
                unsigned b00, b01, b10, b11;
                unsigned addr = ks_u + (((n0 * 8 + bf_row) * KPAD) + kc * 8 + bf_col) * 4;
                ldsm4(b00, b01, b10, b11, addr);
                mma_tf32(sf[n0], qa[kc], b00, b01);
                mma_tf32(sf[n0 + 1], qa[kc], b10, b11);
            }
        }

        if (k0 + 64 > SEQ) {
            int lim = SEQ - k0;
#pragma unroll
            for (int n = 0; n < 8; n++) {
                int c0 = n * 8 + 2 * t;
                if (c0 >= lim) { sf[n][0] = -1e30f; sf[n][2] = -1e30f; }
                if (c0 + 1 >= lim) { sf[n][1] = -1e30f; sf[n][3] = -1e30f; }
            }
        }

        // online softmax
        float tm0 = -1e30f, tm1 = -1e30f;
#pragma unroll
        for (int n = 0; n < 8; n++) {
            tm0 = fmaxf(tm0, fmaxf(sf[n][0], sf[n][1]));
            tm1 = fmaxf(tm1, fmaxf(sf[n][2], sf[n][3]));
        }
        tm0 = fmaxf(tm0, __shfl_xor_sync(0xffffffffu, tm0, 1));
        tm0 = fmaxf(tm0, __shfl_xor_sync(0xffffffffu, tm0, 2));
        tm1 = fmaxf(tm1, __shfl_xor_sync(0xffffffffu, tm1, 1));
        tm1 = fmaxf(tm1, __shfl_xor_sync(0xffffffffu, tm1, 2));
        float mn0 = fmaxf(mi[0], tm0);
        float mn1 = fmaxf(mi[1], tm1);
        float a0 = __expf(mi[0] - mn0);
        float a1 = __expf(mi[1] - mn1);
        float rs0 = 0.f, rs1 = 0.f;
#pragma unroll
        for (int n = 0; n < 8; n++) {
            float p0 = __expf(sf[n][0] - mn0);
            float p1 = __expf(sf[n][1] - mn0);
            float p2 = __expf(sf[n][2] - mn1);
            float p3 = __expf(sf[n][3] - mn1);
            rs0 += p0 + p1;
            rs1 += p2 + p3;
            float2 lo = make_float2(to_tf32(p0), to_tf32(p1));
            float2 hi = make_float2(to_tf32(p2), to_tf32(p3));
            *reinterpret_cast<float2*>(&Ps[(pr + g) * KPAD + n * 8 + 2 * t]) = lo;
            *reinterpret_cast<float2*>(&Ps[(pr + g + 8) * KPAD + n * 8 + 2 * t]) = hi;
        }
        rs0 += __shfl_xor_sync(0xffffffffu, rs0, 1);
        rs0 += __shfl_xor_sync(0xffffffffu, rs0, 2);
        rs1 += __shfl_xor_sync(0xffffffffu, rs1, 1);
        rs1 += __shfl_xor_sync(0xffffffffu, rs1, 2);
        li[0] = li[0] * a0 + rs0;
        li[1] = li[1] * a1 + rs1;
        mi[0] = mn0;
        mi[1] = mn1;
#pragma unroll
        for (int n = 0; n < 8; n++) {
            oc[n][0] *= a0; oc[n][1] *= a0;
            oc[n][2] *= a1; oc[n][3] *= a1;
        }
        __syncwarp();

        // ---- O += P V via ldmatrix (P A-frags + Vt B-frags) ----
#pragma unroll
        for (int kc = 0; kc < 8; kc++) {
            unsigned pa[4];
            {
                unsigned addr = ps_u + ((pa_row * KPAD) + kc * 8 + pa_col) * 4;
                ldsm4(pa[0], pa[1], pa[2], pa[3], addr);
            }
#pragma unroll
            for (int n0 = 0; n0 < 8; n0 += 2) {
                unsigned b00, b01, b10, b11;
                unsigned addr = vt_u + (((n0 * 8 + bf_row) * VTPAD) + kc * 8 + bf_col) * 4;
                ldsm4(b00, b01, b10, b11, addr);
                mma_tf32(oc[n0], pa, b00, b01);
                mma_tf32(oc[n0 + 1], pa, b10, b11);
            }
        }
        __syncthreads();
    }

    const int b = bh >> 2;
    const int h = bh & 3;
    float inv0 = 1.f / li[0];
    float inv1 = 1.f / li[1];
    int qr0 = q0 + pr + g;
    int qr1 = qr0 + 8;
#pragma unroll
    for (int n = 0; n < 8; n++) {
        int d = h * 64 + n * 8 + 2 * t;
        if (qr0 < SEQ) {
            float2 o2 = make_float2(oc[n][0] * inv0, oc[n][1] * inv0);
            *reinterpret_cast<float2*>(&O[((size_t)(b * SEQ + qr0)) * DMODEL + d]) = o2;
        }
        if (qr1 < SEQ) {
            float2 o2 = make_float2(oc[n][2] * inv1, oc[n][3] * inv1);
            *reinterpret_cast<float2*>(&O[((size_t)(b * SEQ + qr1)) * DMODEL + d]) = o2;
        }
    }
}

// ---------------- block stats helper ----------------
__device__ __forceinline__ void block_stats(float v, float* r1, float* r2,
                                            int d, float& mean, float& rstd) {
    __syncthreads();
    float s1 = v, s2 = v * v;
#pragma unroll
    for (int off = 16; off; off >>= 1) {
        s1 += __shfl_xor_sync(0xffffffffu, s1, off);
        s2 += __shfl_xor_sync(0xffffffffu, s2, off);
    }
    int warp = d >> 5, lane = d & 31;
    if (lane == 0) { r1[warp] = s1; r2[warp] = s2; }
    __syncthreads();
    if (d < 8) {
        float a = r1[d], b2 = r2[d];
#pragma unroll
        for (int off = 4; off; off >>= 1) {
            a += __shfl_xor_sync(0xffu, a, off);
            b2 += __shfl_xor_sync(0xffu, b2, off);
        }
        if (d == 0) { r1[0] = a; r2[0] = b2; }
    }
    __syncthreads();
    mean = r1[0] * (1.f / DMODEL);
    float var = r2[0] * (1.f / DMODEL) - mean * mean;
    rstd = rsqrtf(var + LN_EPS);
}

// ---------------- LayerNorm (R may be null) ----------------
__global__ void resid_ln(const float* __restrict__ X, const float* __restrict__ R,
                         const float* __restrict__ sc, const float* __restrict__ bi,
                         float* __restrict__ out) {
    int row = blockIdx.x;
    int d = threadIdx.x;
    size_t base = (size_t)row * DMODEL;
    float v = X[base + d];
    if (R) v += R[base + d];
    __shared__ float r1[8], r2[8];
    float mean, rstd;
    block_stats(v, r1, r2, d, mean, rstd);
    out[base + d] = (v - mean) * rstd * sc[d] + bi[d];
}

// ---------------- LN + LN fused (R may be null) ----------------
__global__ void resid_ln2(const float* __restrict__ X, const float* __restrict__ R,
                          const float* __restrict__ s1c, const float* __restrict__ b1c,
                          const float* __restrict__ s2c, const float* __restrict__ b2c,
                          float* __restrict__ out) {
    int row = blockIdx.x;
    int d = threadIdx.x;
    size_t base = (size_t)row * DMODEL;
    float v = X[base + d];
    if (R) v += R[base + d];
    __shared__ float r1[8], r2[8];
    float mean, rstd;
    block_stats(v, r1, r2, d, mean, rstd);
    float u = (v - mean) * rstd * s1c[d] + b1c[d];
    block_stats(u, r1, r2, d, mean, rstd);
    out[base + d] = (u - mean) * rstd * s2c[d] + b2c[d];
}

// ---------------- partial mean over sequence ----------------
__global__ void mean_part(const float* __restrict__ Y, float* __restrict__ part) {
    int b = blockIdx.x;
    int c = blockIdx.y;
    int d = threadIdx.x;
    const int CH = (SEQ + 7) / 8;
    int s0 = c * CH;
    int s1 = min(SEQ, s0 + CH);
    float acc = 0.f;
    for (int s = s0; s < s1; s++)
        acc += Y[((size_t)b * SEQ + s) * DMODEL + d];
    part[(size_t)(b * 8 + c) * DMODEL + d] = acc;
}

// ---------------- classifier ----------------
__global__ void classifier(const float* __restrict__ part, const float* __restrict__ Wc,
                           const float* __restrict__ bc, float* __restrict__ out) {
    int t = threadIdx.x;
    int pair = t >> 5;
    int lane = t & 31;
    int b = pair >> 1, c = pair & 1;
    float acc = 0.f;
    for (int d = lane; d < DMODEL; d += 32) {
        float m = 0.f;
#pragma unroll
        for (int p = 0; p < 8; p++) m += part[(size_t)(b * 8 + p) * DMODEL + d];
        acc += m * Wc[c * DMODEL + d];
    }
#pragma unroll
    for (int off = 16; off; off >>= 1)
        acc += __shfl_xor_sync(0xffffffffu, acc, off);
    if (lane == 0) out[b * 2 + c] = acc * (1.f / SEQ) + bc[c];
}

// ---------------- launcher ----------------
static float* sym(const void* s) {
    void* p = nullptr;
    cudaGetSymbolAddress(&p, s);
    return (float*)p;
}

extern "C" void kernel_launch(void* const* d_in, const int* in_sizes, int n_in,
                              void* d_out, int out_size) {
    const int* C       = (const int*)d_in[0];
    const float* F     = (const float*)d_in[1];
    const float* W_fnn = (const float*)d_in[2];
    const float* b_fnn = (const float*)d_in[3];
    const float* in_w  = (const float*)d_in[4];
    const float* in_b  = (const float*)d_in[5];
    const float* out_w = (const float*)d_in[6];
    const float* out_b = (const float*)d_in[7];
    const float* ln1s  = (const float*)d_in[8];
    const float* ln1b  = (const float*)d_in[9];
    const float* W1    = (const float*)d_in[10];
    const float* b1    = (const float*)d_in[11];
    const float* W2    = (const float*)d_in[12];
    const float* b2    = (const float*)d_in[13];
    const float* ln2s  = (const float*)d_in[14];
    const float* ln2b  = (const float*)d_in[15];
    const float* ons   = (const float*)d_in[16];
    const float* onb   = (const float*)d_in[17];
    const float* Wc    = (const float*)d_in[18];
    const float* bc    = (const float*)d_in[19];
    float* out = (float*)d_out;

    float* pQ    = sym(g_Q);
    float* px    = sym(g_x);
    float* px2   = sym(g_x2);
    float* pq    = sym(g_q);
    float* pk    = sym(g_k);
    float* pv    = sym(g_v);
    float* po    = sym(g_o);
    float* pt    = sym(g_t);
    float* ph    = sym(g_h);
    float* py    = sym(g_y);
    float* ppart = sym(g_part);

    cudaFuncSetAttribute(flash_tf32, cudaFuncAttributeMaxDynamicSharedMemorySize, FA_SMEM);
    cudaFuncSetAttribute(gemm2t, cudaFuncAttributeMaxDynamicSharedMemorySize, G_SMEM);
    cudaFuncSetAttribute(gemm64, cudaFuncAttributeMaxDynamicSharedMemorySize, H_SMEM);

    // 1) ROI embedding: Q = gelu(F @ W_fnn^T + b)   (6528 x 256, K=1632) -- 64-tile
    {
        dim3 grid(DMODEL / 64, (ROWS_Q + 63) / 64);
        gemm64<<<grid, 128, H_SMEM>>>(F, W_fnn, b_fnn, pQ, ROWS_Q, DMODEL, DIN, 1, nullptr);
    }
    // 2) gather + sum-pool -> tokens
    {
        dim3 grid(SEQ, BATCH);
        gather_pool<<<grid, DMODEL>>>(pQ, C, px);
    }
    // 3) qkv projection fused with head-split + q-scale (13500 x 768, K=256)
    {
        dim3 grid((3 * DMODEL) / GBN, (ROWS_X + GBM - 1) / GBM);
        gemm2t<<<grid, 256, G_SMEM>>>(px, in_w, in_b, nullptr, ROWS_X, 3 * DMODEL, DMODEL, 2,
                                      pq, pk, pv);
    }
    // 4) attention (tf32 flash, ldmatrix fragments)
    {
        dim3 grid((SEQ + 63) / 64, BATCH * NHEAD);
        flash_tf32<<<grid, 128, FA_SMEM>>>(pq, pk, pv, po);
    }
    // 5) out projection + residual (13500 x 256, K=256) -- 64-tile, act=3
    {
        dim3 grid(DMODEL / 64, (ROWS_X + 63) / 64);
        gemm64<<<grid, 128, H_SMEM>>>(po, out_w, out_b, pt, ROWS_X, DMODEL, DMODEL, 3, px);
    }
    // 6) x = LN(pt)
    resid_ln<<<ROWS_X, DMODEL>>>(pt, nullptr, ln1s, ln1b, px2);
    // 7) FFN1: h = gelu(x @ W1^T + b1)   (13500 x 1024, K=256)
    {
        dim3 grid(DFF / GBN, (ROWS_X + GBM - 1) / GBM);
        gemm2t<<<grid, 256, G_SMEM>>>(px2, W1, b1, ph, ROWS_X, DFF, DMODEL, 1,
                                      nullptr, nullptr, nullptr);
    }
    // 8) FFN2 + residual: t = h @ W2^T + b2 + x2   (13500 x 256, K=1024) -- 64-tile, act=3
    {
        dim3 grid(DMODEL / 64, (ROWS_X + 63) / 64);
        gemm64<<<grid, 128, H_SMEM>>>(ph, W2, b2, pt, ROWS_X, DMODEL, DFF, 3, px2);
    }
    // 9+10) x = LN(pt; ln2) then y = LN(x; on)  -- fused
    resid_ln2<<<ROWS_X, DMODEL>>>(pt, nullptr, ln2s, ln2b, ons, onb, py);
    // 11) mean over sequence
    {
        dim3 grid(BATCH, 8);
        mean_part<<<grid, DMODEL>>>(py, ppart);
    }
    // 12) classifier
    classifier<<<1, 256>>>(ppart, Wc, bc, out);
}

// round 15
// speedup vs baseline: 1.1194x; 1.1194x over previous
#include <cuda_runtime.h>
#include <cuda_bf16.h>
#include <math.h>

// ---------------- problem constants ----------------
#define BATCH 4
#define NROI 1632
#define DIN 1632
#define DMODEL 256
#define NHEAD 4
#define DHEAD 64
#define DFF 1024
#define SEQ 3375          // 15^3
#define ROWS_X (BATCH*SEQ)   // 13500
#define ROWS_Q (BATCH*NROI)  // 6528
#define LN_EPS 1e-5f

// ---------------- scratch (device globals; no allocation allowed) ----------------
__device__ float g_Q[ROWS_Q * DMODEL];
__device__ float g_x[ROWS_X * DMODEL];
__device__ float g_x2[ROWS_X * DMODEL];
__device__ float g_q[BATCH * NHEAD * SEQ * DHEAD];
__device__ float g_k[BATCH * NHEAD * SEQ * DHEAD];
__device__ float g_v[BATCH * NHEAD * SEQ * DHEAD];
__device__ float g_o[ROWS_X * DMODEL];
__device__ float g_t[ROWS_X * DMODEL];
__device__ float g_h[ROWS_X * DFF];
__device__ float g_y[ROWS_X * DMODEL];
__device__ float g_part[BATCH * 8 * DMODEL];

// ---------------- helpers ----------------
__device__ __forceinline__ float gelu_exact(float x) {
    return 0.5f * x * (1.0f + erff(x * 0.70710678118654752f));
}
__device__ __forceinline__ float to_tf32(float x) {
    float r;
    asm("cvt.rna.tf32.f32 %0, %1;" : "=f"(r) : "f"(x));
    return r;
}
__device__ __forceinline__ void mma_tf32(float* d, const unsigned* a,
                                         unsigned b0, unsigned b1) {
    asm volatile(
        "mma.sync.aligned.m16n8k8.row.col.f32.tf32.tf32.f32 "
        "{%0,%1,%2,%3}, {%4,%5,%6,%7}, {%8,%9}, {%0,%1,%2,%3};\n"
        : "+f"(d[0]), "+f"(d[1]), "+f"(d[2]), "+f"(d[3])
        : "r"(a[0]), "r"(a[1]), "r"(a[2]), "r"(a[3]), "r"(b0), "r"(b1));
}
// hi/lo split of a float4 into interleaved {h,l} pairs (A operand: exact split).
__device__ __forceinline__ void hl4(float4 v, float4& o0, float4& o1) {
    float hx = to_tf32(v.x), hy = to_tf32(v.y), hz = to_tf32(v.z), hw = to_tf32(v.w);
    o0 = make_float4(hx, v.x - hx, hy, v.y - hy);
    o1 = make_float4(hz, v.z - hz, hw, v.w - hw);
}
__device__ __forceinline__ float4 tf4(float4 v) {
    return make_float4(to_tf32(v.x), to_tf32(v.y), to_tf32(v.z), to_tf32(v.w));
}

// ---------------- tensor-core 2xTF32 GEMM, double-buffered ----------------
// A split hi/lo (exact, interleaved pairs); B rounded once to tf32 (RNA).
// acc += a_hi*b + a_lo*b  ->  error only from B rounding (~2^-11 rel).
// CTA tile 128x64, BK=16, 256 threads = 8 warps (4m x 2n), warp tile 32x32.
// act: 0 = none, 1 = gelu, 2 = qkv-split epilogue, 3 = add residual R.
#define GBM 128
#define GBN 64
#define GBK 16
#define GSTRA 40
#define GSTRB 20
#define G_A (GBM * GSTRA)
#define G_Bf (GBN * GSTRB)
#define G_BUF (G_A + G_Bf)
#define G_SMEM (2 * G_BUF * 4)

__global__ void __launch_bounds__(256, 2)
gemm2t(const float* __restrict__ A, const float* __restrict__ B,
       const float* __restrict__ bias, float* __restrict__ C,
       int M, int N, int K, int act,
       float* __restrict__ qp, float* __restrict__ kp, float* __restrict__ vp,
       const float* __restrict__ R) {
    extern __shared__ float smg[];

    const int bm = blockIdx.y * GBM;
    const int bn = blockIdx.x * GBN;
    const int tid = threadIdx.x;
    const int warp = tid >> 5, lane = tid & 31;
    const int g = lane >> 2, t = lane & 3;
    const int wm = warp >> 1, wn = warp & 1;

    const int am = tid >> 1, ac = tid & 1;
    const int bnr = tid >> 2, bq = tid & 3;
    const int arow = bm + am;
    const int brow = bn + bnr;

    float acc[2][4][4];
#pragma unroll
    for (int mi = 0; mi < 2; mi++)
#pragma unroll
        for (int ni = 0; ni < 4; ni++)
#pragma unroll
            for (int v = 0; v < 4; v++) acc[mi][ni][v] = 0.f;

    const int niter = K / GBK;

    float4 ra0, ra1, rb;
    {
        ra0 = make_float4(0.f, 0.f, 0.f, 0.f);
        ra1 = ra0;
        if (arow < M) {
            ra0 = *reinterpret_cast<const float4*>(&A[(size_t)arow * K + 8 * ac]);
            ra1 = *reinterpret_cast<const float4*>(&A[(size_t)arow * K + 8 * ac + 4]);
        }
        rb = *reinterpret_cast<const float4*>(&B[(size_t)brow * K + 4 * bq]);
        float* Abuf = smg;
        float* Bbuf = smg + G_A;
        float4 o0, o1;
        hl4(ra0, o0, o1);
        *reinterpret_cast<float4*>(&Abuf[am * GSTRA + 16 * ac]) = o0;
        *reinterpret_cast<float4*>(&Abuf[am * GSTRA + 16 * ac + 4]) = o1;
        hl4(ra1, o0, o1);
        *reinterpret_cast<float4*>(&Abuf[am * GSTRA + 16 * ac + 8]) = o0;
        *reinterpret_cast<float4*>(&Abuf[am * GSTRA + 16 * ac + 12]) = o1;
        *reinterpret_cast<float4*>(&Bbuf[bnr * GSTRB + 4 * bq]) = tf4(rb);
    }
    __syncthreads();

    for (int it = 0; it < niter; it++) {
        const int buf = it & 1;
        const bool have_next = (it + 1 < niter);
        if (have_next) {
            int k0 = (it + 1) * GBK;
            ra0 = make_float4(0.f, 0.f, 0.f, 0.f);
            ra1 = ra0;
            if (arow < M) {
                ra0 = *reinterpret_cast<const float4*>(&A[(size_t)arow * K + k0 + 8 * ac]);
                ra1 = *reinterpret_cast<const float4*>(&A[(size_t)arow * K + k0 + 8 * ac + 4]);
            }
            rb = *reinterpret_cast<const float4*>(&B[(size_t)brow * K + k0 + 4 * bq]);
        }

        {
            const float2* A2 = reinterpret_cast<const float2*>(smg + buf * G_BUF);
            const float* Bs = smg + buf * G_BUF + G_A;
#pragma unroll
            for (int kc = 0; kc < 2; kc++) {
                unsigned ah[2][4], al[2][4];
#pragma unroll
                for (int mi = 0; mi < 2; mi++) {
                    int m0 = wm * 32 + mi * 16;
                    int kk = kc * 8 + t;
                    float2 p;
                    p = A2[(m0 + g) * 20 + kk];
                    ah[mi][0] = __float_as_uint(p.x); al[mi][0] = __float_as_uint(p.y);
                    p = A2[(m0 + g + 8) * 20 + kk];
                    ah[mi][1] = __float_as_uint(p.x); al[mi][1] = __float_as_uint(p.y);
                    p = A2[(m0 + g) * 20 + kk + 4];
                    ah[mi][2] = __float_as_uint(p.x); al[mi][2] = __float_as_uint(p.y);
                    p = A2[(m0 + g + 8) * 20 + kk + 4];
                    ah[mi][3] = __float_as_uint(p.x); al[mi][3] = __float_as_uint(p.y);
                }
                unsigned bh[4][2];
#pragma unroll
                for (int ni = 0; ni < 4; ni++) {
                    int n0 = wn * 32 + ni * 8;
                    int kk = kc * 8 + t;
                    bh[ni][0] = __float_as_uint(Bs[(n0 + g) * GSTRB + kk]);
                    bh[ni][1] = __float_as_uint(Bs[(n0 + g) * GSTRB + kk + 4]);
                }
#pragma unroll
                for (int mi = 0; mi < 2; mi++)
#pragma unroll
                    for (int ni = 0; ni < 4; ni++) {
                        mma_tf32(acc[mi][ni], ah[mi], bh[ni][0], bh[ni][1]);
                        mma_tf32(acc[mi][ni], al[mi], bh[ni][0], bh[ni][1]);
                    }
            }
        }

        if (have_next) {
            float* Abuf = smg + (buf ^ 1) * G_BUF;
            float* Bbuf = Abuf + G_A;
            float4 o0, o1;
            hl4(ra0, o0, o1);
            *reinterpret_cast<float4*>(&Abuf[am * GSTRA + 16 * ac]) = o0;
            *reinterpret_cast<float4*>(&Abuf[am * GSTRA + 16 * ac + 4]) = o1;
            hl4(ra1, o0, o1);
            *reinterpret_cast<float4*>(&Abuf[am * GSTRA + 16 * ac + 8]) = o0;
            *reinterpret_cast<float4*>(&Abuf[am * GSTRA + 16 * ac + 12]) = o1;
            *reinterpret_cast<float4*>(&Bbuf[bnr * GSTRB + 4 * bq]) = tf4(rb);
        }
        __syncthreads();
    }

    if (act != 2) {
#pragma unroll
        for (int mi = 0; mi < 2; mi++) {
            int m0 = bm + wm * 32 + mi * 16;
            int row0 = m0 + g;
            int row1 = m0 + g + 8;
#pragma unroll
            for (int ni = 0; ni < 4; ni++) {
                int col = bn + wn * 32 + ni * 8 + 2 * t;
                float b0 = bias[col], b1 = bias[col + 1];
                if (row0 < M) {
                    float v0 = acc[mi][ni][0] + b0;
                    float v1 = acc[mi][ni][1] + b1;
                    if (act == 1) { v0 = gelu_exact(v0); v1 = gelu_exact(v1); }
                    if (act == 3) {
                        float2 r2 = *reinterpret_cast<const float2*>(&R[(size_t)row0 * N + col]);
                        v0 += r2.x; v1 += r2.y;
                    }
                    *reinterpret_cast<float2*>(&C[(size_t)row0 * N + col]) = make_float2(v0, v1);
                }
                if (row1 < M) {
                    float v2 = acc[mi][ni][2] + b0;
                    float v3 = acc[mi][ni][3] + b1;
                    if (act == 1) { v2 = gelu_exact(v2); v3 = gelu_exact(v3); }
                    if (act == 3) {
                        float2 r2 = *reinterpret_cast<const float2*>(&R[(size_t)row1 * N + col]);
                        v2 += r2.x; v3 += r2.y;
                    }
                    *reinterpret_cast<float2*>(&C[(size_t)row1 * N + col]) = make_float2(v2, v3);
                }
            }
        }
    } else {
        // qkv-split epilogue: N=768; cols [0,256)=q (x0.125), [256,512)=k, [512,768)=v.
#pragma unroll
        for (int mi = 0; mi < 2; mi++) {
            int m0 = bm + wm * 32 + mi * 16;
#pragma unroll
            for (int ni = 0; ni < 4; ni++) {
                int col = bn + wn * 32 + ni * 8 + 2 * t;
                int sec = col >> 8;
                int d = col & 255;
                int h = d >> 6;
                int dh = d & 63;
                float* dst = (sec == 0) ? qp : (sec == 1) ? kp : vp;
                float scale = (sec == 0) ? 0.125f : 1.f;
                float b0 = bias[col], b1 = bias[col + 1];
                int row0 = m0 + g;
                int row1 = m0 + g + 8;
                if (row0 < M) {
                    int b = row0 / SEQ, s = row0 - b * SEQ;
                    size_t base = ((size_t)(b * NHEAD + h) * SEQ + s) * DHEAD + dh;
                    *reinterpret_cast<float2*>(&dst[base]) =
                        make_float2((acc[mi][ni][0] + b0) * scale, (acc[mi][ni][1] + b1) * scale);
                }
                if (row1 < M) {
                    int b = row1 / SEQ, s = row1 - b * SEQ;
                    size_t base = ((size_t)(b * NHEAD + h) * SEQ + s) * DHEAD + dh;
                    *reinterpret_cast<float2*>(&dst[base]) =
                        make_float2((acc[mi][ni][2] + b0) * scale, (acc[mi][ni][3] + b1) * scale);
                }
            }
        }
    }
}

// ---------------- gather + sum-pool ----------------
__global__ void gather_pool(const float* __restrict__ Q, const int* __restrict__ C,
                            float* __restrict__ out) {
    int o = blockIdx.x;
    int b = blockIdx.y;
    int d = threadIdx.x;
    int oz = o % 15;
    int oy = (o / 15) % 15;
    int ox = o / 225;
    const float* Qb = Q + (size_t)b * NROI * DMODEL;
    const int* Cb = C + (size_t)b * 32 * 32 * 32;
    float acc = 0.f;
#pragma unroll
    for (int dx = 0; dx < 3; dx++) {
        int x = 2 * ox + dx;
#pragma unroll
        for (int dy = 0; dy < 3; dy++) {
            int y = 2 * oy + dy;
#pragma unroll
            for (int dz = 0; dz < 3; dz++) {
                int z = 2 * oz + dz;
                int idx = Cb[(x * 32 + y) * 32 + z];
                acc += Qb[(size_t)idx * DMODEL + d];
            }
        }
    }
    out[((size_t)b * SEQ + o) * DMODEL + d] = acc;
}

// ---------------- flash attention (R9-exact, 431us measured) ----------------
#define KPAD 68
#define VPAD 72
#define FA_SMEM ((64*68 + 64*72 + 64*68) * 4)

__global__ void __launch_bounds__(128, 3)
flash_tf32(const float* __restrict__ Qm, const float* __restrict__ Km,
           const float* __restrict__ Vm, float* __restrict__ O) {
    extern __shared__ float sm[];
    float* Ks = sm;
    float* Vs = sm + 64 * KPAD;
    float* Ps = sm + 64 * KPAD + 64 * VPAD;

    const int bh = blockIdx.y;
    const int q0 = blockIdx.x * 64;
    const int tid = threadIdx.x;
    const int warp = tid >> 5;
    const int lane = tid & 31;
    const int g = lane >> 2;
    const int t = lane & 3;

    const float* qb = Qm + (size_t)bh * SEQ * DHEAD;
    const float* kb = Km + (size_t)bh * SEQ * DHEAD;
    const float* vb = Vm + (size_t)bh * SEQ * DHEAD;

#pragma unroll
    for (int it = 0; it < 8; it++) {
        int idx = tid + it * 128;
        int row = idx >> 4;
        int c4 = (idx & 15) << 2;
        float4 v = make_float4(0.f, 0.f, 0.f, 0.f);
        if (q0 + row < SEQ) v = *reinterpret_cast<const float4*>(&qb[(size_t)(q0 + row) * 64 + c4]);
        v.x = to_tf32(v.x); v.y = to_tf32(v.y); v.z = to_tf32(v.z); v.w = to_tf32(v.w);
        *reinterpret_cast<float4*>(&Ps[row * KPAD + c4]) = v;
    }
    __syncthreads();

    const int pr = 16 * warp;
    unsigned qa[8][4];
#pragma unroll
    for (int kc = 0; kc < 8; kc++) {
        qa[kc][0] = __float_as_uint(Ps[(pr + g) * KPAD + kc * 8 + t]);
        qa[kc][1] = __float_as_uint(Ps[(pr + g + 8) * KPAD + kc * 8 + t]);
        qa[kc][2] = __float_as_uint(Ps[(pr + g) * KPAD + kc * 8 + t + 4]);
        qa[kc][3] = __float_as_uint(Ps[(pr + g + 8) * KPAD + kc * 8 + t + 4]);
    }

    float oc[8][4];
    float mi[2] = {-1e30f, -1e30f};
    float li[2] = {0.f, 0.f};
#pragma unroll
    for (int n = 0; n < 8; n++)
#pragma unroll
        for (int v = 0; v < 4; v++) oc[n][v] = 0.f;

    const int nkt = (SEQ + 63) / 64;
    for (int kt = 0; kt < nkt; kt++) {
        int k0 = kt * 64;
#pragma unroll
        for (int it = 0; it < 8; it++) {
            int idx = tid + it * 128;
            int row = idx >> 4;
            int c4 = (idx & 15) << 2;
            float4 kv = make_float4(0.f, 0.f, 0.f, 0.f);
            float4 vv = make_float4(0.f, 0.f, 0.f, 0.f);
            if (k0 + row < SEQ) {
                kv = *reinterpret_cast<const float4*>(&kb[(size_t)(k0 + row) * 64 + c4]);
                vv = *reinterpret_cast<const float4*>(&vb[(size_t)(k0 + row) * 64 + c4]);
            }
            kv.x = to_tf32(kv.x); kv.y = to_tf32(kv.y); kv.z = to_tf32(kv.z); kv.w = to_tf32(kv.w);
            vv.x = to_tf32(vv.x); vv.y = to_tf32(vv.y); vv.z = to_tf32(vv.z); vv.w = to_tf32(vv.w);
            *reinterpret_cast<float4*>(&Ks[row * KPAD + c4]) = kv;
            *reinterpret_cast<float4*>(&Vs[row * VPAD + c4]) = vv;
        }
        __syncthreads();

        float sf[8][4];
#pragma unroll
        for (int n = 0; n < 8; n++) {
            sf[n][0] = sf[n][1] = sf[n][2] = sf[n][3] = 0.f;
#pragma unroll
            for (int kc = 0; kc < 8; kc++) {
                unsigned b0 = __float_as_uint(Ks[(n * 8 + g) * KPAD + kc * 8 + t]);
                unsigned b1 = __float_as_uint(Ks[(n * 8 + g) * KPAD + kc * 8 + t + 4]);
                mma_tf32(sf[n], qa[kc], b0, b1);
            }
        }

        if (k0 + 64 > SEQ) {
            int lim = SEQ - k0;
#pragma unroll
            for (int n = 0; n < 8; n++) {
                int c0 = n * 8 + 2 * t;
                if (c0 >= lim) { sf[n][0] = -1e30f; sf[n][2] = -1e30f; }
                if (c0 + 1 >= lim) { sf[n][1] = -1e30f; sf[n][3] = -1e30f; }
            }
        }

        float tm0 = -1e30f, tm1 = -1e30f;
#pragma unroll
        for (int n = 0; n < 8; n++) {
            tm0 = fmaxf(tm0, fmaxf(sf[n][0], sf[n][1]));
            tm1 = fmaxf(tm1, fmaxf(sf[n][2], sf[n][3]));
        }
        tm0 = fmaxf(tm0, __shfl_xor_sync(0xffffffffu, tm0, 1));
        tm0 = fmaxf(tm0, __shfl_xor_sync(0xffffffffu, tm0, 2));
        tm1 = fmaxf(tm1, __shfl_xor_sync(0xffffffffu, tm1, 1));
        tm1 = fmaxf(tm1, __shfl_xor_sync(0xffffffffu, tm1, 2));
        float mn0 = fmaxf(mi[0], tm0);
        float mn1 = fmaxf(mi[1], tm1);
        float a0 = __expf(mi[0] - mn0);
        float a1 = __expf(mi[1] - mn1);
        float rs0 = 0.f, rs1 = 0.f;
#pragma unroll
        for (int n = 0; n < 8; n++) {
            float p0 = __expf(sf[n][0] - mn0);
            float p1 = __expf(sf[n][1] - mn0);
            float p2 = __expf(sf[n][2] - mn1);
            float p3 = __expf(sf[n][3] - mn1);
            rs0 += p0 + p1;
            rs1 += p2 + p3;
            float2 lo = make_float2(to_tf32(p0), to_tf32(p1));
            float2 hi = make_float2(to_tf32(p2), to_tf32(p3));
            *reinterpret_cast<float2*>(&Ps[(pr + g) * KPAD + n * 8 + 2 * t]) = lo;
            *reinterpret_cast<float2*>(&Ps[(pr + g + 8) * KPAD + n * 8 + 2 * t]) = hi;
        }
        rs0 += __shfl_xor_sync(0xffffffffu, rs0, 1);
        rs0 += __shfl_xor_sync(0xffffffffu, rs0, 2);
        rs1 += __shfl_xor_sync(0xffffffffu, rs1, 1);
        rs1 += __shfl_xor_sync(0xffffffffu, rs1, 2);
        li[0] = li[0] * a0 + rs0;
        li[1] = li[1] * a1 + rs1;
        mi[0] = mn0;
        mi[1] = mn1;
#pragma unroll
        for (int n = 0; n < 8; n++) {
            oc[n][0] *= a0; oc[n][1] *= a0;
            oc[n][2] *= a1; oc[n][3] *= a1;
        }
        __syncwarp();

#pragma unroll
        for (int kc = 0; kc < 8; kc++) {
            unsigned pa[4];
            pa[0] = __float_as_uint(Ps[(pr + g) * KPAD + kc * 8 + t]);
            pa[1] = __float_as_uint(Ps[(pr + g + 8) * KPAD + kc * 8 + t]);
            pa[2] = __float_as_uint(Ps[(pr + g) * KPAD + kc * 8 + t + 4]);
            pa[3] = __float_as_uint(Ps[(pr + g + 8) * KPAD + kc * 8 + t + 4]);
#pragma unroll
            for (int n = 0; n < 8; n++) {
                unsigned b0 = __float_as_uint(Vs[(kc * 8 + t) * VPAD + n * 8 + g]);
                unsigned b1 = __float_as_uint(Vs[(kc * 8 + t + 4) * VPAD + n * 8 + g]);
                mma_tf32(oc[n], pa, b0, b1);
            }
        }
        __syncthreads();
    }

    const int b = bh >> 2;
    const int h = bh & 3;
    float inv0 = 1.f / li[0];
    float inv1 = 1.f / li[1];
    int qr0 = q0 + pr + g;
    int qr1 = qr0 + 8;
#pragma unroll
    for (int n = 0; n < 8; n++) {
        int d = h * 64 + n * 8 + 2 * t;
        if (qr0 < SEQ) {
            float2 o2 = make_float2(oc[n][0] * inv0, oc[n][1] * inv0);
            *reinterpret_cast<float2*>(&O[((size_t)(b * SEQ + qr0)) * DMODEL + d]) = o2;
        }
        if (qr1 < SEQ) {
            float2 o2 = make_float2(oc[n][2] * inv1, oc[n][3] * inv1);
            *reinterpret_cast<float2*>(&O[((size_t)(b * SEQ + qr1)) * DMODEL + d]) = o2;
        }
    }
}

// ---------------- block stats helper ----------------
__device__ __forceinline__ void block_stats(float v, float* r1, float* r2,
                                            int d, float& mean, float& rstd) {
    __syncthreads();
    float s1 = v, s2 = v * v;
#pragma unroll
    for (int off = 16; off; off >>= 1) {
        s1 += __shfl_xor_sync(0xffffffffu, s1, off);
        s2 += __shfl_xor_sync(0xffffffffu, s2, off);
    }
    int warp = d >> 5, lane = d & 31;
    if (lane == 0) { r1[warp] = s1; r2[warp] = s2; }
    __syncthreads();
    if (d < 8) {
        float a = r1[d], b2 = r2[d];
#pragma unroll
        for (int off = 4; off; off >>= 1) {
            a += __shfl_xor_sync(0xffu, a, off);
            b2 += __shfl_xor_sync(0xffu, b2, off);
        }
        if (d == 0) { r1[0] = a; r2[0] = b2; }
    }
    __syncthreads();
    mean = r1[0] * (1.f / DMODEL);
    float var = r2[0] * (1.f / DMODEL) - mean * mean;
    rstd = rsqrtf(var + LN_EPS);
}

// ---------------- LayerNorm (R may be null) ----------------
__global__ void resid_ln(const float* __restrict__ X, const float* __restrict__ R,
                         const float* __restrict__ sc, const float* __restrict__ bi,
                         float* __restrict__ out) {
    int row = blockIdx.x;
    int d = threadIdx.x;
    size_t base = (size_t)row * DMODEL;
    float v = X[base + d];
    if (R) v += R[base + d];
    __shared__ float r1[8], r2[8];
    float mean, rstd;
    block_stats(v, r1, r2, d, mean, rstd);
    out[base + d] = (v - mean) * rstd * sc[d] + bi[d];
}

// ---------------- LN + LN fused (R may be null) ----------------
__global__ void resid_ln2(const float* __restrict__ X, const float* __restrict__ R,
                          const float* __restrict__ s1c, const float* __restrict__ b1c,
                          const float* __restrict__ s2c, const float* __restrict__ b2c,
                          float* __restrict__ out) {
    int row = blockIdx.x;
    int d = threadIdx.x;
    size_t base = (size_t)row * DMODEL;
    float v = X[base + d];
    if (R) v += R[base + d];
    __shared__ float r1[8], r2[8];
    float mean, rstd;
    block_stats(v, r1, r2, d, mean, rstd);
    float u = (v - mean) * rstd * s1c[d] + b1c[d];
    block_stats(u, r1, r2, d, mean, rstd);
    out[base + d] = (u - mean) * rstd * s2c[d] + b2c[d];
}

// ---------------- partial mean over sequence ----------------
__global__ void mean_part(const float* __restrict__ Y, float* __restrict__ part) {
    int b = blockIdx.x;
    int c = blockIdx.y;
    int d = threadIdx.x;
    const int CH = (SEQ + 7) / 8;
    int s0 = c * CH;
    int s1 = min(SEQ, s0 + CH);
    float acc = 0.f;
    for (int s = s0; s < s1; s++)
        acc += Y[((size_t)b * SEQ + s) * DMODEL + d];
    part[(size_t)(b * 8 + c) * DMODEL + d] = acc;
}

// ---------------- classifier ----------------
__global__ void classifier(const float* __restrict__ part, const float* __restrict__ Wc,
                           const float* __restrict__ bc, float* __restrict__ out) {
    int t = threadIdx.x;
    int pair = t >> 5;
    int lane = t & 31;
    int b = pair >> 1, c = pair & 1;
    float acc = 0.f;
    for (int d = lane; d < DMODEL; d += 32) {
        float m = 0.f;
#pragma unroll
        for (int p = 0; p < 8; p++) m += part[(size_t)(b * 8 + p) * DMODEL + d];
        acc += m * Wc[c * DMODEL + d];
    }
#pragma unroll
    for (int off = 16; off; off >>= 1)
        acc += __shfl_xor_sync(0xffffffffu, acc, off);
    if (lane == 0) out[b * 2 + c] = acc * (1.f / SEQ) + bc[c];
}

// ---------------- launcher ----------------
static float* sym(const void* s) {
    void* p = nullptr;
    cudaGetSymbolAddress(&p, s);
    return (float*)p;
}

extern "C" void kernel_launch(void* const* d_in, const int* in_sizes, int n_in,
                              void* d_out, int out_size) {
    const int* C       = (const int*)d_in[0];
    const float* F     = (const float*)d_in[1];
    const float* W_fnn = (const float*)d_in[2];
    const float* b_fnn = (const float*)d_in[3];
    const float* in_w  = (const float*)d_in[4];
    const float* in_b  = (const float*)d_in[5];
    const float* out_w = (const float*)d_in[6];
    const float* out_b = (const float*)d_in[7];
    const float* ln1s  = (const float*)d_in[8];
    const float* ln1b  = (const float*)d_in[9];
    const float* W1    = (const float*)d_in[10];
    const float* b1    = (const float*)d_in[11];
    const float* W2    = (const float*)d_in[12];
    const float* b2    = (const float*)d_in[13];
    const float* ln2s  = (const float*)d_in[14];
    const float* ln2b  = (const float*)d_in[15];
    const float* ons   = (const float*)d_in[16];
    const float* onb   = (const float*)d_in[17];
    const float* Wc    = (const float*)d_in[18];
    const float* bc    = (const float*)d_in[19];
    float* out = (float*)d_out;

    float* pQ    = sym(g_Q);
    float* px    = sym(g_x);
    float* px2   = sym(g_x2);
    float* pq    = sym(g_q);
    float* pk    = sym(g_k);
    float* pv    = sym(g_v);
    float* po    = sym(g_o);
    float* pt    = sym(g_t);
    float* ph    = sym(g_h);
    float* py    = sym(g_y);
    float* ppart = sym(g_part);

    cudaFuncSetAttribute(flash_tf32, cudaFuncAttributeMaxDynamicSharedMemorySize, FA_SMEM);
    cudaFuncSetAttribute(gemm2t, cudaFuncAttributeMaxDynamicSharedMemorySize, G_SMEM);

    // 1) ROI embedding: Q = gelu(F @ W_fnn^T + b)   (6528 x 256, K=1632)
    {
        dim3 grid(DMODEL / GBN, (ROWS_Q + GBM - 1) / GBM);
        gemm2t<<<grid, 256, G_SMEM>>>(F, W_fnn, b_fnn, pQ, ROWS_Q, DMODEL, DIN, 1,
                                      nullptr, nullptr, nullptr, nullptr);
    }
    // 2) gather + sum-pool -> tokens
    {
        dim3 grid(SEQ, BATCH);
        gather_pool<<<grid, DMODEL>>>(pQ, C, px);
    }
    // 3) qkv projection fused with head-split + q-scale (13500 x 768, K=256)
    {
        dim3 grid((3 * DMODEL) / GBN, (ROWS_X + GBM - 1) / GBM);
        gemm2t<<<grid, 256, G_SMEM>>>(px, in_w, in_b, nullptr, ROWS_X, 3 * DMODEL, DMODEL, 2,
                                      pq, pk, pv, nullptr);
    }
    // 4) attention (tf32 tensor-core flash, 64-query tiles)
    {
        dim3 grid((SEQ + 63) / 64, BATCH * NHEAD);
        flash_tf32<<<grid, 128, FA_SMEM>>>(pq, pk, pv, po);
    }
    // 5) out projection + residual (13500 x 256, K=256), act=3
    {
        dim3 grid(DMODEL / GBN, (ROWS_X + GBM - 1) / GBM);
        gemm2t<<<grid, 256, G_SMEM>>>(po, out_w, out_b, pt, ROWS_X, DMODEL, DMODEL, 3,
                                      nullptr, nullptr, nullptr, px);
    }
    // 6) x = LN(pt)   (residual already added in epilogue)
    resid_ln<<<ROWS_X, DMODEL>>>(pt, nullptr, ln1s, ln1b, px2);
    // 7) FFN1: h = gelu(x @ W1^T + b1)   (13500 x 1024, K=256)
    {
        dim3 grid(DFF / GBN, (ROWS_X + GBM - 1) / GBM);
        gemm2t<<<grid, 256, G_SMEM>>>(px2, W1, b1, ph, ROWS_X, DFF, DMODEL, 1,
                                      nullptr, nullptr, nullptr, nullptr);
    }
    // 8) FFN2 + residual: t = h @ W2^T + b2 + x2   (13500 x 256, K=1024), act=3
    {
        dim3 grid(DMODEL / GBN, (ROWS_X + GBM - 1) / GBM);
        gemm2t<<<grid, 256, G_SMEM>>>(ph, W2, b2, pt, ROWS_X, DMODEL, DFF, 3,
                                      nullptr, nullptr, nullptr, px2);
    }
    // 9+10) x = LN(pt; ln2) then y = LN(x; on)  -- fused
    resid_ln2<<<ROWS_X, DMODEL>>>(pt, nullptr, ln2s, ln2b, ons, onb, py);
    // 11) mean over sequence
    {
        dim3 grid(BATCH, 8);
        mean_part<<<grid, DMODEL>>>(py, ppart);
    }
    // 12) classifier
    classifier<<<1, 256>>>(ppart, Wc, bc, out);
}

// round 16
// speedup vs baseline: 1.2332x; 1.1016x over previous
#include <cuda_runtime.h>
#include <cuda_bf16.h>
#include <math.h>

// ---------------- problem constants ----------------
#define BATCH 4
#define NROI 1632
#define DIN 1632
#define DMODEL 256
#define NHEAD 4
#define DHEAD 64
#define DFF 1024
#define SEQ 3375          // 15^3
#define ROWS_X (BATCH*SEQ)   // 13500
#define ROWS_Q (BATCH*NROI)  // 6528
#define LN_EPS 1e-5f

// ---------------- scratch (device globals; no allocation allowed) ----------------
__device__ float g_Q[ROWS_Q * DMODEL];
__device__ float g_x[ROWS_X * DMODEL];
__device__ float g_x2[ROWS_X * DMODEL];
__device__ float g_q[BATCH * NHEAD * SEQ * DHEAD];
__device__ float g_k[BATCH * NHEAD * SEQ * DHEAD];
__device__ float g_v[BATCH * NHEAD * SEQ * DHEAD];
__device__ float g_o[ROWS_X * DMODEL];
__device__ float g_t[ROWS_X * DMODEL];
__device__ float g_h[ROWS_X * DFF];
__device__ float g_y[ROWS_X * DMODEL];
__device__ float g_part[BATCH * 8 * DMODEL];

// ---------------- helpers ----------------
__device__ __forceinline__ float gelu_exact(float x) {
    return 0.5f * x * (1.0f + erff(x * 0.70710678118654752f));
}
__device__ __forceinline__ float to_tf32(float x) {
    float r;
    asm("cvt.rna.tf32.f32 %0, %1;" : "=f"(r) : "f"(x));
    return r;
}
__device__ __forceinline__ void mma_tf32(float* d, const unsigned* a,
                                         unsigned b0, unsigned b1) {
    asm volatile(
        "mma.sync.aligned.m16n8k8.row.col.f32.tf32.tf32.f32 "
        "{%0,%1,%2,%3}, {%4,%5,%6,%7}, {%8,%9}, {%0,%1,%2,%3};\n"
        : "+f"(d[0]), "+f"(d[1]), "+f"(d[2]), "+f"(d[3])
        : "r"(a[0]), "r"(a[1]), "r"(a[2]), "r"(a[3]), "r"(b0), "r"(b1));
}
// bf16 m16n8k16 mma, fp32 accumulate
__device__ __forceinline__ void mma_bf16(float* d, const unsigned* a, const unsigned* b) {
    asm volatile(
        "mma.sync.aligned.m16n8k16.row.col.f32.bf16.bf16.f32 "
        "{%0,%1,%2,%3}, {%4,%5,%6,%7}, {%8,%9}, {%0,%1,%2,%3};\n"
        : "+f"(d[0]), "+f"(d[1]), "+f"(d[2]), "+f"(d[3])
        : "r"(a[0]), "r"(a[1]), "r"(a[2]), "r"(a[3]), "r"(b[0]), "r"(b[1]));
}
// pack 2 floats (even=low half, odd=high half) into bf16x2
__device__ __forceinline__ unsigned pack_bf2(float e, float o) {
    unsigned r;
    asm("cvt.rn.bf16x2.f32 %0, %1, %2;" : "=r"(r) : "f"(o), "f"(e));
    return r;
}
// hi bf16x2 word + residual-lo bf16x2 word for a float pair
__device__ __forceinline__ void bfhl(float e, float o, unsigned& hw, unsigned& lw) {
    hw = pack_bf2(e, o);
    float he = __uint_as_float(hw << 16);
    float ho = __uint_as_float(hw & 0xffff0000u);
    lw = pack_bf2(e - he, o - ho);
}
__device__ __forceinline__ float4 tf4(float4 v) {
    return make_float4(to_tf32(v.x), to_tf32(v.y), to_tf32(v.z), to_tf32(v.w));
}

// ---------------- tensor-core bf16x3 GEMM, double-buffered ----------------
// A = Ahi + Alo (bf16 each), B = Bhi + Blo; acc += AhiBh + AloBh + AhiBl.
// Error ~2^-17 per product (better than fp32 GEMM noise floor matters here).
// CTA tile 128x64, BK=16 (one m16n8k16), 256 threads = 8 warps, warp tile 32x32.
// smem planes packed bf16x2, row stride 12 words (conflict-free 12g+t pattern).
// act: 0 = none, 1 = gelu, 2 = qkv-split epilogue, 3 = add residual R.
#define GBM 128
#define GBN 64
#define GBK 16
#define BSTR 12                        // words per row
#define B_A (GBM * BSTR)               // 1536 words per A plane
#define B_B (GBN * BSTR)               // 768 words per B plane
#define B_BUF (2 * B_A + 2 * B_B)      // 4608 words per buffer
#define G_SMEM (2 * B_BUF * 4)         // 36864 B

__global__ void __launch_bounds__(256, 2)
gemm2t(const float* __restrict__ A, const float* __restrict__ B,
       const float* __restrict__ bias, float* __restrict__ C,
       int M, int N, int K, int act,
       float* __restrict__ qp, float* __restrict__ kp, float* __restrict__ vp,
       const float* __restrict__ R) {
    extern __shared__ unsigned smw[];

    const int bm = blockIdx.y * GBM;
    const int bn = blockIdx.x * GBN;
    const int tid = threadIdx.x;
    const int warp = tid >> 5, lane = tid & 31;
    const int g = lane >> 2, t = lane & 3;
    const int wm = warp >> 1, wn = warp & 1;

    const int am = tid >> 1, ac = tid & 1;   // A staging: row, k-half (8 floats)
    const int bnr = tid >> 2, bq = tid & 3;  // B staging: row, k-quarter (4 floats)
    const int arow = bm + am;
    const int brow = bn + bnr;

    float acc[2][4][4];
#pragma unroll
    for (int mi = 0; mi < 2; mi++)
#pragma unroll
        for (int ni = 0; ni < 4; ni++)
#pragma unroll
            for (int v = 0; v < 4; v++) acc[mi][ni][v] = 0.f;

    const int niter = K / GBK;

    float4 ra0, ra1, rb;
    // ---- prologue: load + stage tile 0 ----
    {
        ra0 = make_float4(0.f, 0.f, 0.f, 0.f);
        ra1 = ra0;
        if (arow < M) {
            ra0 = *reinterpret_cast<const float4*>(&A[(size_t)arow * K + 8 * ac]);
            ra1 = *reinterpret_cast<const float4*>(&A[(size_t)arow * K + 8 * ac + 4]);
        }
        rb = *reinterpret_cast<const float4*>(&B[(size_t)brow * K + 4 * bq]);
        unsigned* Ah = smw;
        unsigned* Al = Ah + B_A;
        unsigned* Bh = Al + B_A;
        unsigned* Bl = Bh + B_B;
        unsigned h0, l0, h1, l1, h2, l2, h3, l3;
        bfhl(ra0.x, ra0.y, h0, l0);
        bfhl(ra0.z, ra0.w, h1, l1);
        bfhl(ra1.x, ra1.y, h2, l2);
        bfhl(ra1.z, ra1.w, h3, l3);
        *reinterpret_cast<uint4*>(&Ah[am * BSTR + 4 * ac]) = make_uint4(h0, h1, h2, h3);
        *reinterpret_cast<uint4*>(&Al[am * BSTR + 4 * ac]) = make_uint4(l0, l1, l2, l3);
        bfhl(rb.x, rb.y, h0, l0);
        bfhl(rb.z, rb.w, h1, l1);
        *reinterpret_cast<uint2*>(&Bh[bnr * BSTR + 2 * bq]) = make_uint2(h0, h1);
        *reinterpret_cast<uint2*>(&Bl[bnr * BSTR + 2 * bq]) = make_uint2(l0, l1);
    }
    __syncthreads();

    for (int it = 0; it < niter; it++) {
        const int buf = it & 1;
        const bool have_next = (it + 1 < niter);
        // ---- prefetch next tile into registers ----
        if (have_next) {
            int k0 = (it + 1) * GBK;
            ra0 = make_float4(0.f, 0.f, 0.f, 0.f);
            ra1 = ra0;
            if (arow < M) {
                ra0 = *reinterpret_cast<const float4*>(&A[(size_t)arow * K + k0 + 8 * ac]);
                ra1 = *reinterpret_cast<const float4*>(&A[(size_t)arow * K + k0 + 8 * ac + 4]);
            }
            rb = *reinterpret_cast<const float4*>(&B[(size_t)brow * K + k0 + 4 * bq]);
        }

        // ---- compute on current buffer ----
        {
            const unsigned* Ah = smw + buf * B_BUF;
            const unsigned* Al = Ah + B_A;
            const unsigned* Bh = Al + B_A;
            const unsigned* Bl = Bh + B_B;
            unsigned ah[2][4], al[2][4];
#pragma unroll
            for (int mi = 0; mi < 2; mi++) {
                int m0 = wm * 32 + mi * 16;
                ah[mi][0] = Ah[(m0 + g) * BSTR + t];
                ah[mi][1] = Ah[(m0 + g + 8) * BSTR + t];
                ah[mi][2] = Ah[(m0 + g) * BSTR + t + 4];
                ah[mi][3] = Ah[(m0 + g + 8) * BSTR + t + 4];
                al[mi][0] = Al[(m0 + g) * BSTR + t];
                al[mi][1] = Al[(m0 + g + 8) * BSTR + t];
                al[mi][2] = Al[(m0 + g) * BSTR + t + 4];
                al[mi][3] = Al[(m0 + g + 8) * BSTR + t + 4];
            }
            unsigned bh[4][2], bl[4][2];
#pragma unroll
            for (int ni = 0; ni < 4; ni++) {
                int n0 = wn * 32 + ni * 8;
                bh[ni][0] = Bh[(n0 + g) * BSTR + t];
                bh[ni][1] = Bh[(n0 + g) * BSTR + t + 4];
                bl[ni][0] = Bl[(n0 + g) * BSTR + t];
                bl[ni][1] = Bl[(n0 + g) * BSTR + t + 4];
            }
#pragma unroll
            for (int mi = 0; mi < 2; mi++)
#pragma unroll
                for (int ni = 0; ni < 4; ni++) {
                    mma_bf16(acc[mi][ni], ah[mi], bh[ni]);
                    mma_bf16(acc[mi][ni], al[mi], bh[ni]);
                    mma_bf16(acc[mi][ni], ah[mi], bl[ni]);
                }
        }

        // ---- store prefetched tile into alternate buffer ----
        if (have_next) {
            unsigned* Ah = smw + (buf ^ 1) * B_BUF;
            unsigned* Al = Ah + B_A;
            unsigned* Bh = Al + B_A;
            unsigned* Bl = Bh + B_B;
            unsigned h0, l0, h1, l1, h2, l2, h3, l3;
            bfhl(ra0.x, ra0.y, h0, l0);
            bfhl(ra0.z, ra0.w, h1, l1);
            bfhl(ra1.x, ra1.y, h2, l2);
            bfhl(ra1.z, ra1.w, h3, l3);
            *reinterpret_cast<uint4*>(&Ah[am * BSTR + 4 * ac]) = make_uint4(h0, h1, h2, h3);
            *reinterpret_cast<uint4*>(&Al[am * BSTR + 4 * ac]) = make_uint4(l0, l1, l2, l3);
            bfhl(rb.x, rb.y, h0, l0);
            bfhl(rb.z, rb.w, h1, l1);
            *reinterpret_cast<uint2*>(&Bh[bnr * BSTR + 2 * bq]) = make_uint2(h0, h1);
            *reinterpret_cast<uint2*>(&Bl[bnr * BSTR + 2 * bq]) = make_uint2(l0, l1);
        }
        __syncthreads();
    }

    // ---- epilogue (identical accumulator layout to tf32 version) ----
    if (act != 2) {
#pragma unroll
        for (int mi = 0; mi < 2; mi++) {
            int m0 = bm + wm * 32 + mi * 16;
            int row0 = m0 + g;
            int row1 = m0 + g + 8;
#pragma unroll
            for (int ni = 0; ni < 4; ni++) {
                int col = bn + wn * 32 + ni * 8 + 2 * t;
                float b0 = bias[col], b1 = bias[col + 1];
                if (row0 < M) {
                    float v0 = acc[mi][ni][0] + b0;
                    float v1 = acc[mi][ni][1] + b1;
                    if (act == 1) { v0 = gelu_exact(v0); v1 = gelu_exact(v1); }
                    if (act == 3) {
                        float2 r2 = *reinterpret_cast<const float2*>(&R[(size_t)row0 * N + col]);
                        v0 += r2.x; v1 += r2.y;
                    }
                    *reinterpret_cast<float2*>(&C[(size_t)row0 * N + col]) = make_float2(v0, v1);
                }
                if (row1 < M) {
                    float v2 = acc[mi][ni][2] + b0;
                    float v3 = acc[mi][ni][3] + b1;
                    if (act == 1) { v2 = gelu_exact(v2); v3 = gelu_exact(v3); }
                    if (act == 3) {
                        float2 r2 = *reinterpret_cast<const float2*>(&R[(size_t)row1 * N + col]);
                        v2 += r2.x; v3 += r2.y;
                    }
                    *reinterpret_cast<float2*>(&C[(size_t)row1 * N + col]) = make_float2(v2, v3);
                }
            }
        }
    } else {
        // qkv-split epilogue: N=768; cols [0,256)=q (x0.125), [256,512)=k, [512,768)=v.
#pragma unroll
        for (int mi = 0; mi < 2; mi++) {
            int m0 = bm + wm * 32 + mi * 16;
#pragma unroll
            for (int ni = 0; ni < 4; ni++) {
                int col = bn + wn * 32 + ni * 8 + 2 * t;
                int sec = col >> 8;
                int d = col & 255;
                int h = d >> 6;
                int dh = d & 63;
                float* dst = (sec == 0) ? qp : (sec == 1) ? kp : vp;
                float scale = (sec == 0) ? 0.125f : 1.f;
                float b0 = bias[col], b1 = bias[col + 1];
                int row0 = m0 + g;
                int row1 = m0 + g + 8;
                if (row0 < M) {
                    int b = row0 / SEQ, s = row0 - b * SEQ;
                    size_t base = ((size_t)(b * NHEAD + h) * SEQ + s) * DHEAD + dh;
                    *reinterpret_cast<float2*>(&dst[base]) =
                        make_float2((acc[mi][ni][0] + b0) * scale, (acc[mi][ni][1] + b1) * scale);
                }
                if (row1 < M) {
                    int b = row1 / SEQ, s = row1 - b * SEQ;
                    size_t base = ((size_t)(b * NHEAD + h) * SEQ + s) * DHEAD + dh;
                    *reinterpret_cast<float2*>(&dst[base]) =
                        make_float2((acc[mi][ni][2] + b0) * scale, (acc[mi][ni][3] + b1) * scale);
                }
            }
        }
    }
}

// ---------------- gather + sum-pool ----------------
__global__ void gather_pool(const float* __restrict__ Q, const int* __restrict__ C,
                            float* __restrict__ out) {
    int o = blockIdx.x;
    int b = blockIdx.y;
    int d = threadIdx.x;
    int oz = o % 15;
    int oy = (o / 15) % 15;
    int ox = o / 225;
    const float* Qb = Q + (size_t)b * NROI * DMODEL;
    const int* Cb = C + (size_t)b * 32 * 32 * 32;
    float acc = 0.f;
#pragma unroll
    for (int dx = 0; dx < 3; dx++) {
        int x = 2 * ox + dx;
#pragma unroll
        for (int dy = 0; dy < 3; dy++) {
            int y = 2 * oy + dy;
#pragma unroll
            for (int dz = 0; dz < 3; dz++) {
                int z = 2 * oz + dz;
                int idx = Cb[(x * 32 + y) * 32 + z];
                acc += Qb[(size_t)idx * DMODEL + d];
            }
        }
    }
    out[((size_t)b * SEQ + o) * DMODEL + d] = acc;
}

// ---------------- flash attention (R9-exact, 431us measured) ----------------
#define KPAD 68
#define VPAD 72
#define FA_SMEM ((64*68 + 64*72 + 64*68) * 4)

__global__ void __launch_bounds__(128, 3)
flash_tf32(const float* __restrict__ Qm, const float* __restrict__ Km,
           const float* __restrict__ Vm, float* __restrict__ O) {
    extern __shared__ float sm[];
    float* Ks = sm;
    float* Vs = sm + 64 * KPAD;
    float* Ps = sm + 64 * KPAD + 64 * VPAD;

    const int bh = blockIdx.y;
    const int q0 = blockIdx.x * 64;
    const int tid = threadIdx.x;
    const int warp = tid >> 5;
    const int lane = tid & 31;
    const int g = lane >> 2;
    const int t = lane & 3;

    const float* qb = Qm + (size_t)bh * SEQ * DHEAD;
    const float* kb = Km + (size_t)bh * SEQ * DHEAD;
    const float* vb = Vm + (size_t)bh * SEQ * DHEAD;

#pragma unroll
    for (int it = 0; it < 8; it++) {
        int idx = tid + it * 128;
        int row = idx >> 4;
        int c4 = (idx & 15) << 2;
        float4 v = make_float4(0.f, 0.f, 0.f, 0.f);
        if (q0 + row < SEQ) v = *reinterpret_cast<const float4*>(&qb[(size_t)(q0 + row) * 64 + c4]);
        v.x = to_tf32(v.x); v.y = to_tf32(v.y); v.z = to_tf32(v.z); v.w = to_tf32(v.w);
        *reinterpret_cast<float4*>(&Ps[row * KPAD + c4]) = v;
    }
    __syncthreads();

    const int pr = 16 * warp;
    unsigned qa[8][4];
#pragma unroll
    for (int kc = 0; kc < 8; kc++) {
        qa[kc][0] = __float_as_uint(Ps[(pr + g) * KPAD + kc * 8 + t]);
        qa[kc][1] = __float_as_uint(Ps[(pr + g + 8) * KPAD + kc * 8 + t]);
        qa[kc][2] = __float_as_uint(Ps[(pr + g) * KPAD + kc * 8 + t + 4]);
        qa[kc][3] = __float_as_uint(Ps[(pr + g + 8) * KPAD + kc * 8 + t + 4]);
    }

    float oc[8][4];
    float mi[2] = {-1e30f, -1e30f};
    float li[2] = {0.f, 0.f};
#pragma unroll
    for (int n = 0; n < 8; n++)
#pragma unroll
        for (int v = 0; v < 4; v++) oc[n][v] = 0.f;

    const int nkt = (SEQ + 63) / 64;
    for (int kt = 0; kt < nkt; kt++) {
        int k0 = kt * 64;
#pragma unroll
        for (int it = 0; it < 8; it++) {
            int idx = tid + it * 128;
            int row = idx >> 4;
            int c4 = (idx & 15) << 2;
            float4 kv = make_float4(0.f, 0.f, 0.f, 0.f);
            float4 vv = make_float4(0.f, 0.f, 0.f, 0.f);
            if (k0 + row < SEQ) {
                kv = *reinterpret_cast<const float4*>(&kb[(size_t)(k0 + row) * 64 + c4]);
                vv = *reinterpret_cast<const float4*>(&vb[(size_t)(k0 + row) * 64 + c4]);
            }
            kv.x = to_tf32(kv.x); kv.y = to_tf32(kv.y); kv.z = to_tf32(kv.z); kv.w = to_tf32(kv.w);
            vv.x = to_tf32(vv.x); vv.y = to_tf32(vv.y); vv.z = to_tf32(vv.z); vv.w = to_tf32(vv.w);
            *reinterpret_cast<float4*>(&Ks[row * KPAD + c4]) = kv;
            *reinterpret_cast<float4*>(&Vs[row * VPAD + c4]) = vv;
        }
        __syncthreads();

        float sf[8][4];
#pragma unroll
        for (int n = 0; n < 8; n++) {
            sf[n][0] = sf[n][1] = sf[n][2] = sf[n][3] = 0.f;
#pragma unroll
            for (int kc = 0; kc < 8; kc++) {
                unsigned b0 = __float_as_uint(Ks[(n * 8 + g) * KPAD + kc * 8 + t]);
                unsigned b1 = __float_as_uint(Ks[(n * 8 + g) * KPAD + kc * 8 + t + 4]);
                mma_tf32(sf[n], qa[kc], b0, b1);
            }
        }

        if (k0 + 64 > SEQ) {
            int lim = SEQ - k0;
#pragma unroll
            for (int n = 0; n < 8; n++) {
                int c0 = n * 8 + 2 * t;
                if (c0 >= lim) { sf[n][0] = -1e30f; sf[n][2] = -1e30f; }
                if (c0 + 1 >= lim) { sf[n][1] = -1e30f; sf[n][3] = -1e30f; }
            }
        }

        float tm0 = -1e30f, tm1 = -1e30f;
#pragma unroll
        for (int n = 0; n < 8; n++) {
            tm0 = fmaxf(tm0, fmaxf(sf[n][0], sf[n][1]));
            tm1 = fmaxf(tm1, fmaxf(sf[n][2], sf[n][3]));
        }
        tm0 = fmaxf(tm0, __shfl_xor_sync(0xffffffffu, tm0, 1));
        tm0 = fmaxf(tm0, __shfl_xor_sync(0xffffffffu, tm0, 2));
        tm1 = fmaxf(tm1, __shfl_xor_sync(0xffffffffu, tm1, 1));
        tm1 = fmaxf(tm1, __shfl_xor_sync(0xffffffffu, tm1, 2));
        float mn0 = fmaxf(mi[0], tm0);
        float mn1 = fmaxf(mi[1], tm1);
        float a0 = __expf(mi[0] - mn0);
        float a1 = __expf(mi[1] - mn1);
        float rs0 = 0.f, rs1 = 0.f;
#pragma unroll
        for (int n = 0; n < 8; n++) {
            float p0 = __expf(sf[n][0] - mn0);
            float p1 = __expf(sf[n][1] - mn0);
            float p2 = __expf(sf[n][2] - mn1);
            float p3 = __expf(sf[n][3] - mn1);
            rs0 += p0 + p1;
            rs1 += p2 + p3;
            float2 lo = make_float2(to_tf32(p0), to_tf32(p1));
            float2 hi = make_float2(to_tf32(p2), to_tf32(p3));
            *reinterpret_cast<float2*>(&Ps[(pr + g) * KPAD + n * 8 + 2 * t]) = lo;
            *reinterpret_cast<float2*>(&Ps[(pr + g + 8) * KPAD + n * 8 + 2 * t]) = hi;
        }
        rs0 += __shfl_xor_sync(0xffffffffu, rs0, 1);
        rs0 += __shfl_xor_sync(0xffffffffu, rs0, 2);
        rs1 += __shfl_xor_sync(0xffffffffu, rs1, 1);
        rs1 += __shfl_xor_sync(0xffffffffu, rs1, 2);
        li[0] = li[0] * a0 + rs0;
        li[1] = li[1] * a1 + rs1;
        mi[0] = mn0;
        mi[1] = mn1;
#pragma unroll
        for (int n = 0; n < 8; n++) {
            oc[n][0] *= a0; oc[n][1] *= a0;
            oc[n][2] *= a1; oc[n][3] *= a1;
        }
        __syncwarp();

#pragma unroll
        for (int kc = 0; kc < 8; kc++) {
            unsigned pa[4];
            pa[0] = __float_as_uint(Ps[(pr + g) * KPAD + kc * 8 + t]);
            pa[1] = __float_as_uint(Ps[(pr + g + 8) * KPAD + kc * 8 + t]);
            pa[2] = __float_as_uint(Ps[(pr + g) * KPAD + kc * 8 + t + 4]);
            pa[3] = __float_as_uint(Ps[(pr + g + 8) * KPAD + kc * 8 + t + 4]);
#pragma unroll
            for (int n = 0; n < 8; n++) {
                unsigned b0 = __float_as_uint(Vs[(kc * 8 + t) * VPAD + n * 8 + g]);
                unsigned b1 = __float_as_uint(Vs[(kc * 8 + t + 4) * VPAD + n * 8 + g]);
                mma_tf32(oc[n], pa, b0, b1);
            }
        }
        __syncthreads();
    }

    const int b = bh >> 2;
    const int h = bh & 3;
    float inv0 = 1.f / li[0];
    float inv1 = 1.f / li[1];
    int qr0 = q0 + pr + g;
    int qr1 = qr0 + 8;
#pragma unroll
    for (int n = 0; n < 8; n++) {
        int d = h * 64 + n * 8 + 2 * t;
        if (qr0 < SEQ) {
            float2 o2 = make_float2(oc[n][0] * inv0, oc[n][1] * inv0);
            *reinterpret_cast<float2*>(&O[((size_t)(b * SEQ + qr0)) * DMODEL + d]) = o2;
        }
        if (qr1 < SEQ) {
            float2 o2 = make_float2(oc[n][2] * inv1, oc[n][3] * inv1);
            *reinterpret_cast<float2*>(&O[((size_t)(b * SEQ + qr1)) * DMODEL + d]) = o2;
        }
    }
}

// ---------------- block stats helper ----------------
__device__ __forceinline__ void block_stats(float v, float* r1, float* r2,
                                            int d, float& mean, float& rstd) {
    __syncthreads();
    float s1 = v, s2 = v * v;
#pragma unroll
    for (int off = 16; off; off >>= 1) {
        s1 += __shfl_xor_sync(0xffffffffu, s1, off);
        s2 += __shfl_xor_sync(0xffffffffu, s2, off);
    }
    int warp = d >> 5, lane = d & 31;
    if (lane == 0) { r1[warp] = s1; r2[warp] = s2; }
    __syncthreads();
    if (d < 8) {
        float a = r1[d], b2 = r2[d];
#pragma unroll
        for (int off = 4; off; off >>= 1) {
            a += __shfl_xor_sync(0xffu, a, off);
            b2 += __shfl_xor_sync(0xffu, b2, off);
        }
        if (d == 0) { r1[0] = a; r2[0] = b2; }
    }
    __syncthreads();
    mean = r1[0] * (1.f / DMODEL);
    float var = r2[0] * (1.f / DMODEL) - mean * mean;
    rstd = rsqrtf(var + LN_EPS);
}

// ---------------- LayerNorm (R may be null) ----------------
__global__ void resid_ln(const float* __restrict__ X, const float* __restrict__ R,
                         const float* __restrict__ sc, const float* __restrict__ bi,
                         float* __restrict__ out) {
    int row = blockIdx.x;
    int d = threadIdx.x;
    size_t base = (size_t)row * DMODEL;
    float v = X[base + d];
    if (R) v += R[base + d];
    __shared__ float r1[8], r2[8];
    float mean, rstd;
    block_stats(v, r1, r2, d, mean, rstd);
    out[base + d] = (v - mean) * rstd * sc[d] + bi[d];
}

// ---------------- LN + LN fused (R may be null) ----------------
__global__ void resid_ln2(const float* __restrict__ X, const float* __restrict__ R,
                          const float* __restrict__ s1c, const float* __restrict__ b1c,
                          const float* __restrict__ s2c, const float* __restrict__ b2c,
                          float* __restrict__ out) {
    int row = blockIdx.x;
    int d = threadIdx.x;
    size_t base = (size_t)row * DMODEL;
    float v = X[base + d];
    if (R) v += R[base + d];
    __shared__ float r1[8], r2[8];
    float mean, rstd;
    block_stats(v, r1, r2, d, mean, rstd);
    float u = (v - mean) * rstd * s1c[d] + b1c[d];
    block_stats(u, r1, r2, d, mean, rstd);
    out[base + d] = (u - mean) * rstd * s2c[d] + b2c[d];
}

// ---------------- partial mean over sequence ----------------
__global__ void mean_part(const float* __restrict__ Y, float* __restrict__ part) {
    int b = blockIdx.x;
    int c = blockIdx.y;
    int d = threadIdx.x;
    const int CH = (SEQ + 7) / 8;
    int s0 = c * CH;
    int s1 = min(SEQ, s0 + CH);
    float acc = 0.f;
    for (int s = s0; s < s1; s++)
        acc += Y[((size_t)b * SEQ + s) * DMODEL + d];
    part[(size_t)(b * 8 + c) * DMODEL + d] = acc;
}

// ---------------- classifier ----------------
__global__ void classifier(const float* __restrict__ part, const float* __restrict__ Wc,
                           const float* __restrict__ bc, float* __restrict__ out) {
    int t = threadIdx.x;
    int pair = t >> 5;
    int lane = t & 31;
    int b = pair >> 1, c = pair & 1;
    float acc = 0.f;
    for (int d = lane; d < DMODEL; d += 32) {
        float m = 0.f;
#pragma unroll
        for (int p = 0; p < 8; p++) m += part[(size_t)(b * 8 + p) * DMODEL + d];
        acc += m * Wc[c * DMODEL + d];
    }
#pragma unroll
    for (int off = 16; off; off >>= 1)
        acc += __shfl_xor_sync(0xffffffffu, acc, off);
    if (lane == 0) out[b * 2 + c] = acc * (1.f / SEQ) + bc[c];
}

// ---------------- launcher ----------------
static float* sym(const void* s) {
    void* p = nullptr;
    cudaGetSymbolAddress(&p, s);
    return (float*)p;
}

extern "C" void kernel_launch(void* const* d_in, const int* in_sizes, int n_in,
                              void* d_out, int out_size) {
    const int* C       = (const int*)d_in[0];
    const float* F     = (const float*)d_in[1];
    const float* W_fnn = (const float*)d_in[2];
    const float* b_fnn = (const float*)d_in[3];
    const float* in_w  = (const float*)d_in[4];
    const float* in_b  = (const float*)d_in[5];
    const float* out_w = (const float*)d_in[6];
    const float* out_b = (const float*)d_in[7];
    const float* ln1s  = (const float*)d_in[8];
    const float* ln1b  = (const float*)d_in[9];
    const float* W1    = (const float*)d_in[10];
    const float* b1    = (const float*)d_in[11];
    const float* W2    = (const float*)d_in[12];
    const float* b2    = (const float*)d_in[13];
    const float* ln2s  = (const float*)d_in[14];
    const float* ln2b  = (const float*)d_in[15];
    const float* ons   = (const float*)d_in[16];
    const float* onb   = (const float*)d_in[17];
    const float* Wc    = (const float*)d_in[18];
    const float* bc    = (const float*)d_in[19];
    float* out = (float*)d_out;

    float* pQ    = sym(g_Q);
    float* px    = sym(g_x);
    float* px2   = sym(g_x2);
    float* pq    = sym(g_q);
    float* pk    = sym(g_k);
    float* pv    = sym(g_v);
    float* po    = sym(g_o);
    float* pt    = sym(g_t);
    float* ph    = sym(g_h);
    float* py    = sym(g_y);
    float* ppart = sym(g_part);

    cudaFuncSetAttribute(flash_tf32, cudaFuncAttributeMaxDynamicSharedMemorySize, FA_SMEM);
    cudaFuncSetAttribute(gemm2t, cudaFuncAttributeMaxDynamicSharedMemorySize, G_SMEM);

    // 1) ROI embedding: Q = gelu(F @ W_fnn^T + b)   (6528 x 256, K=1632)
    {
        dim3 grid(DMODEL / GBN, (ROWS_Q + GBM - 1) / GBM);
        gemm2t<<<grid, 256, G_SMEM>>>(F, W_fnn, b_fnn, pQ, ROWS_Q, DMODEL, DIN, 1,
                                      nullptr, nullptr, nullptr, nullptr);
    }
    // 2) gather + sum-pool -> tokens
    {
        dim3 grid(SEQ, BATCH);
        gather_pool<<<grid, DMODEL>>>(pQ, C, px);
    }
    // 3) qkv projection fused with head-split + q-scale (13500 x 768, K=256)
    {
        dim3 grid((3 * DMODEL) / GBN, (ROWS_X + GBM - 1) / GBM);
        gemm2t<<<grid, 256, G_SMEM>>>(px, in_w, in_b, nullptr, ROWS_X, 3 * DMODEL, DMODEL, 2,
                                      pq, pk, pv, nullptr);
    }
    // 4) attention (tf32 tensor-core flash, 64-query tiles)
    {
        dim3 grid((SEQ + 63) / 64, BATCH * NHEAD);
        flash_tf32<<<grid, 128, FA_SMEM>>>(pq, pk, pv, po);
    }
    // 5) out projection + residual (13500 x 256, K=256), act=3
    {
        dim3 grid(DMODEL / GBN, (ROWS_X + GBM - 1) / GBM);
        gemm2t<<<grid, 256, G_SMEM>>>(po, out_w, out_b, pt, ROWS_X, DMODEL, DMODEL, 3,
                                      nullptr, nullptr, nullptr, px);
    }
    // 6) x = LN(pt)   (residual already added in epilogue)
    resid_ln<<<ROWS_X, DMODEL>>>(pt, nullptr, ln1s, ln1b, px2);
    // 7) FFN1: h = gelu(x @ W1^T + b1)   (13500 x 1024, K=256)
    {
        dim3 grid(DFF / GBN, (ROWS_X + GBM - 1) / GBM);
        gemm2t<<<grid, 256, G_SMEM>>>(px2, W1, b1, ph, ROWS_X, DFF, DMODEL, 1,
                                      nullptr, nullptr, nullptr, nullptr);
    }
    // 8) FFN2 + residual: t = h @ W2^T + b2 + x2   (13500 x 256, K=1024), act=3
    {
        dim3 grid(DMODEL / GBN, (ROWS_X + GBM - 1) / GBM);
        gemm2t<<<grid, 256, G_SMEM>>>(ph, W2, b2, pt, ROWS_X, DMODEL, DFF, 3,
                                      nullptr, nullptr, nullptr, px2);
    }
    // 9+10) x = LN(pt; ln2) then y = LN(x; on)  -- fused
    resid_ln2<<<ROWS_X, DMODEL>>>(pt, nullptr, ln2s, ln2b, ons, onb, py);
    // 11) mean over sequence
    {
        dim3 grid(BATCH, 8);
        mean_part<<<grid, DMODEL>>>(py, ppart);
    }
    // 12) classifier
    classifier<<<1, 256>>>(ppart, Wc, bc, out);
}

// round 17
// speedup vs baseline: 1.2382x; 1.0040x over previous
#include <cuda_runtime.h>
#include <cuda_bf16.h>
#include <math.h>

// ---------------- problem constants ----------------
#define BATCH 4
#define NROI 1632
#define DIN 1632
#define DMODEL 256
#define NHEAD 4
#define DHEAD 64
#define DFF 1024
#define SEQ 3375          // 15^3
#define ROWS_X (BATCH*SEQ)   // 13500
#define ROWS_Q (BATCH*NROI)  // 6528
#define LN_EPS 1e-5f

// ---------------- scratch (device globals; no allocation allowed) ----------------
__device__ float g_Q[ROWS_Q * DMODEL];
__device__ float g_x[ROWS_X * DMODEL];
__device__ float g_x2[ROWS_X * DMODEL];
__device__ float g_q[BATCH * NHEAD * SEQ * DHEAD];
__device__ float g_k[BATCH * NHEAD * SEQ * DHEAD];
__device__ float g_v[BATCH * NHEAD * SEQ * DHEAD];
__device__ float g_o[ROWS_X * DMODEL];
__device__ float g_t[ROWS_X * DMODEL];
__device__ float g_h[ROWS_X * DFF];
__device__ float g_y[ROWS_X * DMODEL];
__device__ float g_part[BATCH * 8 * DMODEL];

// ---------------- helpers ----------------
__device__ __forceinline__ float gelu_exact(float x) {
    return 0.5f * x * (1.0f + erff(x * 0.70710678118654752f));
}
__device__ __forceinline__ float to_tf32(float x) {
    float r;
    asm("cvt.rna.tf32.f32 %0, %1;" : "=f"(r) : "f"(x));
    return r;
}
__device__ __forceinline__ void mma_tf32(float* d, const unsigned* a,
                                         unsigned b0, unsigned b1) {
    asm volatile(
        "mma.sync.aligned.m16n8k8.row.col.f32.tf32.tf32.f32 "
        "{%0,%1,%2,%3}, {%4,%5,%6,%7}, {%8,%9}, {%0,%1,%2,%3};\n"
        : "+f"(d[0]), "+f"(d[1]), "+f"(d[2]), "+f"(d[3])
        : "r"(a[0]), "r"(a[1]), "r"(a[2]), "r"(a[3]), "r"(b0), "r"(b1));
}
// bf16 m16n8k16 mma, fp32 accumulate
__device__ __forceinline__ void mma_bf16(float* d, const unsigned* a, const unsigned* b) {
    asm volatile(
        "mma.sync.aligned.m16n8k16.row.col.f32.bf16.bf16.f32 "
        "{%0,%1,%2,%3}, {%4,%5,%6,%7}, {%8,%9}, {%0,%1,%2,%3};\n"
        : "+f"(d[0]), "+f"(d[1]), "+f"(d[2]), "+f"(d[3])
        : "r"(a[0]), "r"(a[1]), "r"(a[2]), "r"(a[3]), "r"(b[0]), "r"(b[1]));
}
// pack 2 floats (even=low half, odd=high half) into bf16x2
__device__ __forceinline__ unsigned pack_bf2(float e, float o) {
    unsigned r;
    asm("cvt.rn.bf16x2.f32 %0, %1, %2;" : "=r"(r) : "f"(o), "f"(e));
    return r;
}
// hi bf16x2 word + residual-lo bf16x2 word for a float pair
__device__ __forceinline__ void bfhl(float e, float o, unsigned& hw, unsigned& lw) {
    hw = pack_bf2(e, o);
    float he = __uint_as_float(hw << 16);
    float ho = __uint_as_float(hw & 0xffff0000u);
    lw = pack_bf2(e - he, o - ho);
}
__device__ __forceinline__ float4 tf4(float4 v) {
    return make_float4(to_tf32(v.x), to_tf32(v.y), to_tf32(v.z), to_tf32(v.w));
}

// ---------------- tensor-core bf16x3 GEMM, double-buffered, BK=32 ----------------
// A = Ahi + Alo (bf16), B = Bhi + Blo; acc += AhiBh + AloBh + AhiBl.
// CTA tile 128x64, BK=32 (two m16n8k16 groups per buffer), 256 threads, warp tile 32x32.
// Each k16 group lives in its own 12-word-stride sub-plane (conflict-free 12g+t).
// act: 0 = none, 1 = gelu, 2 = qkv-split epilogue, 3 = add residual R.
// Requires K % 32 == 0, N % 64 == 0.
#define GBM 128
#define GBN 64
#define BSTR 12
#define P_A (GBM * BSTR)               // 1536 words per A sub-plane
#define P_B (GBN * BSTR)               // 768 words per B sub-plane
#define B_BUF (4 * P_A + 4 * P_B)      // 9216 words per buffer
#define G_SMEM (2 * B_BUF * 4)         // 73728 B

__global__ void __launch_bounds__(256, 2)
gemm2t(const float* __restrict__ A, const float* __restrict__ B,
       const float* __restrict__ bias, float* __restrict__ C,
       int M, int N, int K, int act,
       float* __restrict__ qp, float* __restrict__ kp, float* __restrict__ vp,
       const float* __restrict__ R) {
    extern __shared__ unsigned smw[];

    const int bm = blockIdx.y * GBM;
    const int bn = blockIdx.x * GBN;
    const int tid = threadIdx.x;
    const int warp = tid >> 5, lane = tid & 31;
    const int g = lane >> 2, t = lane & 3;
    const int wm = warp >> 1, wn = warp & 1;

    const int am = tid >> 1, ac = tid & 1;   // A staging: row, k16-GROUP (16 floats each)
    const int bnr = tid >> 2, bq = tid & 3;  // B staging: row, 8-float chunk
    const int bgr = bq >> 1, bhf = bq & 1;   // B: group, half-within-group
    const int arow = bm + am;
    const int brow = bn + bnr;

    float acc[2][4][4];
#pragma unroll
    for (int mi = 0; mi < 2; mi++)
#pragma unroll
        for (int ni = 0; ni < 4; ni++)
#pragma unroll
            for (int v = 0; v < 4; v++) acc[mi][ni][v] = 0.f;

    const int niter = K >> 5;   // K/32

    float4 ra0, ra1, ra2, ra3, rb0, rb1;
    // ---- stage helper (lambda-style macro via code dup) ----
    // prologue: load + stage tile 0
    {
        ra0 = make_float4(0.f, 0.f, 0.f, 0.f);
        ra1 = ra0; ra2 = ra0; ra3 = ra0;
        if (arow < M) {
            const float* ap = &A[(size_t)arow * K + 16 * ac];
            ra0 = *reinterpret_cast<const float4*>(ap);
            ra1 = *reinterpret_cast<const float4*>(ap + 4);
            ra2 = *reinterpret_cast<const float4*>(ap + 8);
            ra3 = *reinterpret_cast<const float4*>(ap + 12);
        }
        const float* bp = &B[(size_t)brow * K + 8 * bq];
        rb0 = *reinterpret_cast<const float4*>(bp);
        rb1 = *reinterpret_cast<const float4*>(bp + 4);

        unsigned* base = smw;
        unsigned* Ah = base + ac * P_A;            // group = ac
        unsigned* Al = base + 2 * P_A + ac * P_A;
        unsigned* Bh = base + 4 * P_A + bgr * P_B;
        unsigned* Bl = base + 4 * P_A + 2 * P_B + bgr * P_B;
        unsigned h0, l0, h1, l1, h2, l2, h3, l3;
        bfhl(ra0.x, ra0.y, h0, l0);
        bfhl(ra0.z, ra0.w, h1, l1);
        bfhl(ra1.x, ra1.y, h2, l2);
        bfhl(ra1.z, ra1.w, h3, l3);
        *reinterpret_cast<uint4*>(&Ah[am * BSTR]) = make_uint4(h0, h1, h2, h3);
        *reinterpret_cast<uint4*>(&Al[am * BSTR]) = make_uint4(l0, l1, l2, l3);
        bfhl(ra2.x, ra2.y, h0, l0);
        bfhl(ra2.z, ra2.w, h1, l1);
        bfhl(ra3.x, ra3.y, h2, l2);
        bfhl(ra3.z, ra3.w, h3, l3);
        *reinterpret_cast<uint4*>(&Ah[am * BSTR + 4]) = make_uint4(h0, h1, h2, h3);
        *reinterpret_cast<uint4*>(&Al[am * BSTR + 4]) = make_uint4(l0, l1, l2, l3);
        bfhl(rb0.x, rb0.y, h0, l0);
        bfhl(rb0.z, rb0.w, h1, l1);
        bfhl(rb1.x, rb1.y, h2, l2);
        bfhl(rb1.z, rb1.w, h3, l3);
        *reinterpret_cast<uint4*>(&Bh[bnr * BSTR + 4 * bhf]) = make_uint4(h0, h1, h2, h3);
        *reinterpret_cast<uint4*>(&Bl[bnr * BSTR + 4 * bhf]) = make_uint4(l0, l1, l2, l3);
    }
    __syncthreads();

    for (int it = 0; it < niter; it++) {
        const int buf = it & 1;
        const bool have_next = (it + 1 < niter);
        // ---- prefetch next tile ----
        if (have_next) {
            int k0 = (it + 1) << 5;
            ra0 = make_float4(0.f, 0.f, 0.f, 0.f);
            ra1 = ra0; ra2 = ra0; ra3 = ra0;
            if (arow < M) {
                const float* ap = &A[(size_t)arow * K + k0 + 16 * ac];
                ra0 = *reinterpret_cast<const float4*>(ap);
                ra1 = *reinterpret_cast<const float4*>(ap + 4);
                ra2 = *reinterpret_cast<const float4*>(ap + 8);
                ra3 = *reinterpret_cast<const float4*>(ap + 12);
            }
            const float* bp = &B[(size_t)brow * K + k0 + 8 * bq];
            rb0 = *reinterpret_cast<const float4*>(bp);
            rb1 = *reinterpret_cast<const float4*>(bp + 4);
        }

        // ---- compute: two k16 groups ----
        {
            const unsigned* base = smw + buf * B_BUF;
#pragma unroll
            for (int gr = 0; gr < 2; gr++) {
                const unsigned* Ah = base + gr * P_A;
                const unsigned* Al = base + 2 * P_A + gr * P_A;
                const unsigned* Bh = base + 4 * P_A + gr * P_B;
                const unsigned* Bl = base + 4 * P_A + 2 * P_B + gr * P_B;
                unsigned ah[2][4], al[2][4];
#pragma unroll
                for (int mi = 0; mi < 2; mi++) {
                    int m0 = wm * 32 + mi * 16;
                    ah[mi][0] = Ah[(m0 + g) * BSTR + t];
                    ah[mi][1] = Ah[(m0 + g + 8) * BSTR + t];
                    ah[mi][2] = Ah[(m0 + g) * BSTR + t + 4];
                    ah[mi][3] = Ah[(m0 + g + 8) * BSTR + t + 4];
                    al[mi][0] = Al[(m0 + g) * BSTR + t];
                    al[mi][1] = Al[(m0 + g + 8) * BSTR + t];
                    al[mi][2] = Al[(m0 + g) * BSTR + t + 4];
                    al[mi][3] = Al[(m0 + g + 8) * BSTR + t + 4];
                }
                unsigned bh[4][2], bl[4][2];
#pragma unroll
                for (int ni = 0; ni < 4; ni++) {
                    int n0 = wn * 32 + ni * 8;
                    bh[ni][0] = Bh[(n0 + g) * BSTR + t];
                    bh[ni][1] = Bh[(n0 + g) * BSTR + t + 4];
                    bl[ni][0] = Bl[(n0 + g) * BSTR + t];
                    bl[ni][1] = Bl[(n0 + g) * BSTR + t + 4];
                }
#pragma unroll
                for (int mi = 0; mi < 2; mi++)
#pragma unroll
                    for (int ni = 0; ni < 4; ni++) {
                        mma_bf16(acc[mi][ni], ah[mi], bh[ni]);
                        mma_bf16(acc[mi][ni], al[mi], bh[ni]);
                        mma_bf16(acc[mi][ni], ah[mi], bl[ni]);
                    }
            }
        }

        // ---- store prefetched tile into alternate buffer ----
        if (have_next) {
            unsigned* base = smw + (buf ^ 1) * B_BUF;
            unsigned* Ah = base + ac * P_A;
            unsigned* Al = base + 2 * P_A + ac * P_A;
            unsigned* Bh = base + 4 * P_A + bgr * P_B;
            unsigned* Bl = base + 4 * P_A + 2 * P_B + bgr * P_B;
            unsigned h0, l0, h1, l1, h2, l2, h3, l3;
            bfhl(ra0.x, ra0.y, h0, l0);
            bfhl(ra0.z, ra0.w, h1, l1);
            bfhl(ra1.x, ra1.y, h2, l2);
            bfhl(ra1.z, ra1.w, h3, l3);
            *reinterpret_cast<uint4*>(&Ah[am * BSTR]) = make_uint4(h0, h1, h2, h3);
            *reinterpret_cast<uint4*>(&Al[am * BSTR]) = make_uint4(l0, l1, l2, l3);
            bfhl(ra2.x, ra2.y, h0, l0);
            bfhl(ra2.z, ra2.w, h1, l1);
            bfhl(ra3.x, ra3.y, h2, l2);
            bfhl(ra3.z, ra3.w, h3, l3);
            *reinterpret_cast<uint4*>(&Ah[am * BSTR + 4]) = make_uint4(h0, h1, h2, h3);
            *reinterpret_cast<uint4*>(&Al[am * BSTR + 4]) = make_uint4(l0, l1, l2, l3);
            bfhl(rb0.x, rb0.y, h0, l0);
            bfhl(rb0.z, rb0.w, h1, l1);
            bfhl(rb1.x, rb1.y, h2, l2);
            bfhl(rb1.z, rb1.w, h3, l3);
            *reinterpret_cast<uint4*>(&Bh[bnr * BSTR + 4 * bhf]) = make_uint4(h0, h1, h2, h3);
            *reinterpret_cast<uint4*>(&Bl[bnr * BSTR + 4 * bhf]) = make_uint4(l0, l1, l2, l3);
        }
        __syncthreads();
    }

    // ---- epilogue (accumulator layout unchanged) ----
    if (act != 2) {
#pragma unroll
        for (int mi = 0; mi < 2; mi++) {
            int m0 = bm + wm * 32 + mi * 16;
            int row0 = m0 + g;
            int row1 = m0 + g + 8;
#pragma unroll
            for (int ni = 0; ni < 4; ni++) {
                int col = bn + wn * 32 + ni * 8 + 2 * t;
                float b0 = bias[col], b1 = bias[col + 1];
                if (row0 < M) {
                    float v0 = acc[mi][ni][0] + b0;
                    float v1 = acc[mi][ni][1] + b1;
                    if (act == 1) { v0 = gelu_exact(v0); v1 = gelu_exact(v1); }
                    if (act == 3) {
                        float2 r2 = *reinterpret_cast<const float2*>(&R[(size_t)row0 * N + col]);
                        v0 += r2.x; v1 += r2.y;
                    }
                    *reinterpret_cast<float2*>(&C[(size_t)row0 * N + col]) = make_float2(v0, v1);
                }
                if (row1 < M) {
                    float v2 = acc[mi][ni][2] + b0;
                    float v3 = acc[mi][ni][3] + b1;
                    if (act == 1) { v2 = gelu_exact(v2); v3 = gelu_exact(v3); }
                    if (act == 3) {
                        float2 r2 = *reinterpret_cast<const float2*>(&R[(size_t)row1 * N + col]);
                        v2 += r2.x; v3 += r2.y;
                    }
                    *reinterpret_cast<float2*>(&C[(size_t)row1 * N + col]) = make_float2(v2, v3);
                }
            }
        }
    } else {
        // qkv-split epilogue: N=768; cols [0,256)=q (x0.125), [256,512)=k, [512,768)=v.
#pragma unroll
        for (int mi = 0; mi < 2; mi++) {
            int m0 = bm + wm * 32 + mi * 16;
#pragma unroll
            for (int ni = 0; ni < 4; ni++) {
                int col = bn + wn * 32 + ni * 8 + 2 * t;
                int sec = col >> 8;
                int d = col & 255;
                int h = d >> 6;
                int dh = d & 63;
                float* dst = (sec == 0) ? qp : (sec == 1) ? kp : vp;
                float scale = (sec == 0) ? 0.125f : 1.f;
                float b0 = bias[col], b1 = bias[col + 1];
                int row0 = m0 + g;
                int row1 = m0 + g + 8;
                if (row0 < M) {
                    int b = row0 / SEQ, s = row0 - b * SEQ;
                    size_t base = ((size_t)(b * NHEAD + h) * SEQ + s) * DHEAD + dh;
                    *reinterpret_cast<float2*>(&dst[base]) =
                        make_float2((acc[mi][ni][0] + b0) * scale, (acc[mi][ni][1] + b1) * scale);
                }
                if (row1 < M) {
                    int b = row1 / SEQ, s = row1 - b * SEQ;
                    size_t base = ((size_t)(b * NHEAD + h) * SEQ + s) * DHEAD + dh;
                    *reinterpret_cast<float2*>(&dst[base]) =
                        make_float2((acc[mi][ni][2] + b0) * scale, (acc[mi][ni][3] + b1) * scale);
                }
            }
        }
    }
}

// ---------------- gather + sum-pool ----------------
__global__ void gather_pool(const float* __restrict__ Q, const int* __restrict__ C,
                            float* __restrict__ out) {
    int o = blockIdx.x;
    int b = blockIdx.y;
    int d = threadIdx.x;
    int oz = o % 15;
    int oy = (o / 15) % 15;
    int ox = o / 225;
    const float* Qb = Q + (size_t)b * NROI * DMODEL;
    const int* Cb = C + (size_t)b * 32 * 32 * 32;
    float acc = 0.f;
#pragma unroll
    for (int dx = 0; dx < 3; dx++) {
        int x = 2 * ox + dx;
#pragma unroll
        for (int dy = 0; dy < 3; dy++) {
            int y = 2 * oy + dy;
#pragma unroll
            for (int dz = 0; dz < 3; dz++) {
                int z = 2 * oz + dz;
                int idx = Cb[(x * 32 + y) * 32 + z];
                acc += Qb[(size_t)idx * DMODEL + d];
            }
        }
    }
    out[((size_t)b * SEQ + o) * DMODEL + d] = acc;
}

// ---------------- flash attention (R9-exact, 431us measured) ----------------
#define KPAD 68
#define VPAD 72
#define FA_SMEM ((64*68 + 64*72 + 64*68) * 4)

__global__ void __launch_bounds__(128, 3)
flash_tf32(const float* __restrict__ Qm, const float* __restrict__ Km,
           const float* __restrict__ Vm, float* __restrict__ O) {
    extern __shared__ float sm[];
    float* Ks = sm;
    float* Vs = sm + 64 * KPAD;
    float* Ps = sm + 64 * KPAD + 64 * VPAD;

    const int bh = blockIdx.y;
    const int q0 = blockIdx.x * 64;
    const int tid = threadIdx.x;
    const int warp = tid >> 5;
    const int lane = tid & 31;
    const int g = lane >> 2;
    const int t = lane & 3;

    const float* qb = Qm + (size_t)bh * SEQ * DHEAD;
    const float* kb = Km + (size_t)bh * SEQ * DHEAD;
    const float* vb = Vm + (size_t)bh * SEQ * DHEAD;

#pragma unroll
    for (int it = 0; it < 8; it++) {
        int idx = tid + it * 128;
        int row = idx >> 4;
        int c4 = (idx & 15) << 2;
        float4 v = make_float4(0.f, 0.f, 0.f, 0.f);
        if (q0 + row < SEQ) v = *reinterpret_cast<const float4*>(&qb[(size_t)(q0 + row) * 64 + c4]);
        v.x = to_tf32(v.x); v.y = to_tf32(v.y); v.z = to_tf32(v.z); v.w = to_tf32(v.w);
        *reinterpret_cast<float4*>(&Ps[row * KPAD + c4]) = v;
    }
    __syncthreads();

    const int pr = 16 * warp;
    unsigned qa[8][4];
#pragma unroll
    for (int kc = 0; kc < 8; kc++) {
        qa[kc][0] = __float_as_uint(Ps[(pr + g) * KPAD + kc * 8 + t]);
        qa[kc][1] = __float_as_uint(Ps[(pr + g + 8) * KPAD + kc * 8 + t]);
        qa[kc][2] = __float_as_uint(Ps[(pr + g) * KPAD + kc * 8 + t + 4]);
        qa[kc][3] = __float_as_uint(Ps[(pr + g + 8) * KPAD + kc * 8 + t + 4]);
    }

    float oc[8][4];
    float mi[2] = {-1e30f, -1e30f};
    float li[2] = {0.f, 0.f};
#pragma unroll
    for (int n = 0; n < 8; n++)
#pragma unroll
        for (int v = 0; v < 4; v++) oc[n][v] = 0.f;

    const int nkt = (SEQ + 63) / 64;
    for (int kt = 0; kt < nkt; kt++) {
        int k0 = kt * 64;
#pragma unroll
        for (int it = 0; it < 8; it++) {
            int idx = tid + it * 128;
            int row = idx >> 4;
            int c4 = (idx & 15) << 2;
            float4 kv = make_float4(0.f, 0.f, 0.f, 0.f);
            float4 vv = make_float4(0.f, 0.f, 0.f, 0.f);
            if (k0 + row < SEQ) {
                kv = *reinterpret_cast<const float4*>(&kb[(size_t)(k0 + row) * 64 + c4]);
                vv = *reinterpret_cast<const float4*>(&vb[(size_t)(k0 + row) * 64 + c4]);
            }
            kv.x = to_tf32(kv.x); kv.y = to_tf32(kv.y); kv.z = to_tf32(kv.z); kv.w = to_tf32(kv.w);
            vv.x = to_tf32(vv.x); vv.y = to_tf32(vv.y); vv.z = to_tf32(vv.z); vv.w = to_tf32(vv.w);
            *reinterpret_cast<float4*>(&Ks[row * KPAD + c4]) = kv;
            *reinterpret_cast<float4*>(&Vs[row * VPAD + c4]) = vv;
        }
        __syncthreads();

        float sf[8][4];
#pragma unroll
        for (int n = 0; n < 8; n++) {
            sf[n][0] = sf[n][1] = sf[n][2] = sf[n][3] = 0.f;
#pragma unroll
            for (int kc = 0; kc < 8; kc++) {
                unsigned b0 = __float_as_uint(Ks[(n * 8 + g) * KPAD + kc * 8 + t]);
                unsigned b1 = __float_as_uint(Ks[(n * 8 + g) * KPAD + kc * 8 + t + 4]);
                mma_tf32(sf[n], qa[kc], b0, b1);
            }
        }

        if (k0 + 64 > SEQ) {
            int lim = SEQ - k0;
#pragma unroll
            for (int n = 0; n < 8; n++) {
                int c0 = n * 8 + 2 * t;
                if (c0 >= lim) { sf[n][0] = -1e30f; sf[n][2] = -1e30f; }
                if (c0 + 1 >= lim) { sf[n][1] = -1e30f; sf[n][3] = -1e30f; }
            }
        }

        float tm0 = -1e30f, tm1 = -1e30f;
#pragma unroll
        for (int n = 0; n < 8; n++) {
            tm0 = fmaxf(tm0, fmaxf(sf[n][0], sf[n][1]));
            tm1 = fmaxf(tm1, fmaxf(sf[n][2], sf[n][3]));
        }
        tm0 = fmaxf(tm0, __shfl_xor_sync(0xffffffffu, tm0, 1));
        tm0 = fmaxf(tm0, __shfl_xor_sync(0xffffffffu, tm0, 2));
        tm1 = fmaxf(tm1, __shfl_xor_sync(0xffffffffu, tm1, 1));
        tm1 = fmaxf(tm1, __shfl_xor_sync(0xffffffffu, tm1, 2));
        float mn0 = fmaxf(mi[0], tm0);
        float mn1 = fmaxf(mi[1], tm1);
        float a0 = __expf(mi[0] - mn0);
        float a1 = __expf(mi[1] - mn1);
        float rs0 = 0.f, rs1 = 0.f;
#pragma unroll
        for (int n = 0; n < 8; n++) {
            float p0 = __expf(sf[n][0] - mn0);
            float p1 = __expf(sf[n][1] - mn0);
            float p2 = __expf(sf[n][2] - mn1);
            float p3 = __expf(sf[n][3] - mn1);
            rs0 += p0 + p1;
            rs1 += p2 + p3;
            float2 lo = make_float2(to_tf32(p0), to_tf32(p1));
            float2 hi = make_float2(to_tf32(p2), to_tf32(p3));
            *reinterpret_cast<float2*>(&Ps[(pr + g) * KPAD + n * 8 + 2 * t]) = lo;
            *reinterpret_cast<float2*>(&Ps[(pr + g + 8) * KPAD + n * 8 + 2 * t]) = hi;
        }
        rs0 += __shfl_xor_sync(0xffffffffu, rs0, 1);
        rs0 += __shfl_xor_sync(0xffffffffu, rs0, 2);
        rs1 += __shfl_xor_sync(0xffffffffu, rs1, 1);
        rs1 += __shfl_xor_sync(0xffffffffu, rs1, 2);
        li[0] = li[0] * a0 + rs0;
        li[1] = li[1] * a1 + rs1;
        mi[0] = mn0;
        mi[1] = mn1;
#pragma unroll
        for (int n = 0; n < 8; n++) {
            oc[n][0] *= a0; oc[n][1] *= a0;
            oc[n][2] *= a1; oc[n][3] *= a1;
        }
        __syncwarp();

#pragma unroll
        for (int kc = 0; kc < 8; kc++) {
            unsigned pa[4];
            pa[0] = __float_as_uint(Ps[(pr + g) * KPAD + kc * 8 + t]);
            pa[1] = __float_as_uint(Ps[(pr + g + 8) * KPAD + kc * 8 + t]);
            pa[2] = __float_as_uint(Ps[(pr + g) * KPAD + kc * 8 + t + 4]);
            pa[3] = __float_as_uint(Ps[(pr + g + 8) * KPAD + kc * 8 + t + 4]);
#pragma unroll
            for (int n = 0; n < 8; n++) {
                unsigned b0 = __float_as_uint(Vs[(kc * 8 + t) * VPAD + n * 8 + g]);
                unsigned b1 = __float_as_uint(Vs[(kc * 8 + t + 4) * VPAD + n * 8 + g]);
                mma_tf32(oc[n], pa, b0, b1);
            }
        }
        __syncthreads();
    }

    const int b = bh >> 2;
    const int h = bh & 3;
    float inv0 = 1.f / li[0];
    float inv1 = 1.f / li[1];
    int qr0 = q0 + pr + g;
    int qr1 = qr0 + 8;
#pragma unroll
    for (int n = 0; n < 8; n++) {
        int d = h * 64 + n * 8 + 2 * t;
        if (qr0 < SEQ) {
            float2 o2 = make_float2(oc[n][0] * inv0, oc[n][1] * inv0);
            *reinterpret_cast<float2*>(&O[((size_t)(b * SEQ + qr0)) * DMODEL + d]) = o2;
        }
        if (qr1 < SEQ) {
            float2 o2 = make_float2(oc[n][2] * inv1, oc[n][3] * inv1);
            *reinterpret_cast<float2*>(&O[((size_t)(b * SEQ + qr1)) * DMODEL + d]) = o2;
        }
    }
}

// ---------------- block stats helper ----------------
__device__ __forceinline__ void block_stats(float v, float* r1, float* r2,
                                            int d, float& mean, float& rstd) {
    __syncthreads();
    float s1 = v, s2 = v * v;
#pragma unroll
    for (int off = 16; off; off >>= 1) {
        s1 += __shfl_xor_sync(0xffffffffu, s1, off);
        s2 += __shfl_xor_sync(0xffffffffu, s2, off);
    }
    int warp = d >> 5, lane = d & 31;
    if (lane == 0) { r1[warp] = s1; r2[warp] = s2; }
    __syncthreads();
    if (d < 8) {
        float a = r1[d], b2 = r2[d];
#pragma unroll
        for (int off = 4; off; off >>= 1) {
            a += __shfl_xor_sync(0xffu, a, off);
            b2 += __shfl_xor_sync(0xffu, b2, off);
        }
        if (d == 0) { r1[0] = a; r2[0] = b2; }
    }
    __syncthreads();
    mean = r1[0] * (1.f / DMODEL);
    float var = r2[0] * (1.f / DMODEL) - mean * mean;
    rstd = rsqrtf(var + LN_EPS);
}

// ---------------- LayerNorm (R may be null) ----------------
__global__ void resid_ln(const float* __restrict__ X, const float* __restrict__ R,
                         const float* __restrict__ sc, const float* __restrict__ bi,
                         float* __restrict__ out) {
    int row = blockIdx.x;
    int d = threadIdx.x;
    size_t base = (size_t)row * DMODEL;
    float v = X[base + d];
    if (R) v += R[base + d];
    __shared__ float r1[8], r2[8];
    float mean, rstd;
    block_stats(v, r1, r2, d, mean, rstd);
    out[base + d] = (v - mean) * rstd * sc[d] + bi[d];
}

// ---------------- LN + LN fused (R may be null) ----------------
__global__ void resid_ln2(const float* __restrict__ X, const float* __restrict__ R,
                          const float* __restrict__ s1c, const float* __restrict__ b1c,
                          const float* __restrict__ s2c, const float* __restrict__ b2c,
                          float* __restrict__ out) {
    int row = blockIdx.x;
    int d = threadIdx.x;
    size_t base = (size_t)row * DMODEL;
    float v = X[base + d];
    if (R) v += R[base + d];
    __shared__ float r1[8], r2[8];
    float mean, rstd;
    block_stats(v, r1, r2, d, mean, rstd);
    float u = (v - mean) * rstd * s1c[d] + b1c[d];
    block_stats(u, r1, r2, d, mean, rstd);
    out[base + d] = (u - mean) * rstd * s2c[d] + b2c[d];
}

// ---------------- partial mean over sequence ----------------
__global__ void mean_part(const float* __restrict__ Y, float* __restrict__ part) {
    int b = blockIdx.x;
    int c = blockIdx.y;
    int d = threadIdx.x;
    const int CH = (SEQ + 7) / 8;
    int s0 = c * CH;
    int s1 = min(SEQ, s0 + CH);
    float acc = 0.f;
    for (int s = s0; s < s1; s++)
        acc += Y[((size_t)b * SEQ + s) * DMODEL + d];
    part[(size_t)(b * 8 + c) * DMODEL + d] = acc;
}

// ---------------- classifier ----------------
__global__ void classifier(const float* __restrict__ part, const float* __restrict__ Wc,
                           const float* __restrict__ bc, float* __restrict__ out) {
    int t = threadIdx.x;
    int pair = t >> 5;
    int lane = t & 31;
    int b = pair >> 1, c = pair & 1;
    float acc = 0.f;
    for (int d = lane; d < DMODEL; d += 32) {
        float m = 0.f;
#pragma unroll
        for (int p = 0; p < 8; p++) m += part[(size_t)(b * 8 + p) * DMODEL + d];
        acc += m * Wc[c * DMODEL + d];
    }
#pragma unroll
    for (int off = 16; off; off >>= 1)
        acc += __shfl_xor_sync(0xffffffffu, acc, off);
    if (lane == 0) out[b * 2 + c] = acc * (1.f / SEQ) + bc[c];
}

// ---------------- launcher ----------------
static float* sym(const void* s) {
    void* p = nullptr;
    cudaGetSymbolAddress(&p, s);
    return (float*)p;
}

extern "C" void kernel_launch(void* const* d_in, const int* in_sizes, int n_in,
                              void* d_out, int out_size) {
    const int* C       = (const int*)d_in[0];
    const float* F     = (const float*)d_in[1];
    const float* W_fnn = (const float*)d_in[2];
    const float* b_fnn = (const float*)d_in[3];
    const float* in_w  = (const float*)d_in[4];
    const float* in_b  = (const float*)d_in[5];
    const float* out_w = (const float*)d_in[6];
    const float* out_b = (const float*)d_in[7];
    const float* ln1s  = (const float*)d_in[8];
    const float* ln1b  = (const float*)d_in[9];
    const float* W1    = (const float*)d_in[10];
    const float* b1    = (const float*)d_in[11];
    const float* W2    = (const float*)d_in[12];
    const float* b2    = (const float*)d_in[13];
    const float* ln2s  = (const float*)d_in[14];
    const float* ln2b  = (const float*)d_in[15];
    const float* ons   = (const float*)d_in[16];
    const float* onb   = (const float*)d_in[17];
    const float* Wc    = (const float*)d_in[18];
    const float* bc    = (const float*)d_in[19];
    float* out = (float*)d_out;

    float* pQ    = sym(g_Q);
    float* px    = sym(g_x);
    float* px2   = sym(g_x2);
    float* pq    = sym(g_q);
    float* pk    = sym(g_k);
    float* pv    = sym(g_v);
    float* po    = sym(g_o);
    float* pt    = sym(g_t);
    float* ph    = sym(g_h);
    float* py    = sym(g_y);
    float* ppart = sym(g_part);

    cudaFuncSetAttribute(flash_tf32, cudaFuncAttributeMaxDynamicSharedMemorySize, FA_SMEM);
    cudaFuncSetAttribute(gemm2t, cudaFuncAttributeMaxDynamicSharedMemorySize, G_SMEM);

    // 1) ROI embedding: Q = gelu(F @ W_fnn^T + b)   (6528 x 256, K=1632)
    {
        dim3 grid(DMODEL / GBN, (ROWS_Q + GBM - 1) / GBM);
        gemm2t<<<grid, 256, G_SMEM>>>(F, W_fnn, b_fnn, pQ, ROWS_Q, DMODEL, DIN, 1,
                                      nullptr, nullptr, nullptr, nullptr);
    }
    // 2) gather + sum-pool -> tokens
    {
        dim3 grid(SEQ, BATCH);
        gather_pool<<<grid, DMODEL>>>(pQ, C, px);
    }
    // 3) qkv projection fused with head-split + q-scale (13500 x 768, K=256)
    {
        dim3 grid((3 * DMODEL) / GBN, (ROWS_X + GBM - 1) / GBM);
        gemm2t<<<grid, 256, G_SMEM>>>(px, in_w, in_b, nullptr, ROWS_X, 3 * DMODEL, DMODEL, 2,
                                      pq, pk, pv, nullptr);
    }
    // 4) attention (tf32 tensor-core flash, 64-query tiles)
    {
        dim3 grid((SEQ + 63) / 64, BATCH * NHEAD);
        flash_tf32<<<grid, 128, FA_SMEM>>>(pq, pk, pv, po);
    }
    // 5) out projection + residual (13500 x 256, K=256), act=3
    {
        dim3 grid(DMODEL / GBN, (ROWS_X + GBM - 1) / GBM);
        gemm2t<<<grid, 256, G_SMEM>>>(po, out_w, out_b, pt, ROWS_X, DMODEL, DMODEL, 3,
                                      nullptr, nullptr, nullptr, px);
    }
    // 6) x = LN(pt)
    resid_ln<<<ROWS_X, DMODEL>>>(pt, nullptr, ln1s, ln1b, px2);
    // 7) FFN1: h = gelu(x @ W1^T + b1)   (13500 x 1024, K=256)
    {
        dim3 grid(DFF / GBN, (ROWS_X + GBM - 1) / GBM);
        gemm2t<<<grid, 256, G_SMEM>>>(px2, W1, b1, ph, ROWS_X, DFF, DMODEL, 1,
                                      nullptr, nullptr, nullptr, nullptr);
    }
    // 8) FFN2 + residual: t = h @ W2^T + b2 + x2   (13500 x 256, K=1024), act=3
    {
        dim3 grid(DMODEL / GBN, (ROWS_X + GBM - 1) / GBM);
        gemm2t<<<grid, 256, G_SMEM>>>(ph, W2, b2, pt, ROWS_X, DMODEL, DFF, 3,
                                      nullptr, nullptr, nullptr, px2);
    }
    // 9+10) x = LN(pt; ln2) then y = LN(x; on)  -- fused
    resid_ln2<<<ROWS_X, DMODEL>>>(pt, nullptr, ln2s, ln2b, ons, onb, py);
    // 11) mean over sequence
    {
        dim3 grid(BATCH, 8);
        mean_part<<<grid, DMODEL>>>(py, ppart);
    }
    // 12) classifier
    classifier<<<1, 256>>>(ppart, Wc, bc, out);
}